// round 11
// baseline (speedup 1.0000x reference)
#include <cuda_runtime.h>
#include <cuda_bf16.h>
#include <math.h>
#include <stdint.h>

// Problem constants
#define NN 100000
#define EE 600000
#define DD 128
#define RR 4
#define GG 256
#define CC 16
#define KTOT 640          // 128 (h) + 4*128 (per-relation aggregates)
#define NB2 1563          // ceil(NN*RR/256)

// ---------------- device scratch ----------------
__device__ float          g_h0[(size_t)NN * DD];      // 51 MB
__device__ float          g_h1[(size_t)NN * DD];      // 51 MB
__device__ __nv_bfloat16  g_bh[3 * DD * KTOT];        // B hi bf16, [l][n][k]
__device__ __nv_bfloat16  g_bl[3 * DD * KTOT];        // B lo bf16
__device__ int    g_cnt[NN * RR];                     // per (dst,rel) in-degree
__device__ int    g_off[NN * RR];                     // CSR offsets by (dst,rel)
__device__ int    g_fpos[NN * RR];                    // fill tickets
__device__ int    g_bsum[2048];                       // scan partials
__device__ int    g_eidx[EE];                         // src, (dst,rel)-grouped
__device__ float  g_pool[GG * DD];
__device__ float  g_pcnt[GG];

// ---------------- helpers ----------------
__device__ __forceinline__ void red_add_v4(float* addr, float x, float y, float z, float w) {
    asm volatile("red.global.add.v4.f32 [%0], {%1,%2,%3,%4};"
                 :: "l"(addr), "f"(x), "f"(y), "f"(z), "f"(w) : "memory");
}
__device__ __forceinline__ float elu1(float v) { return v > 0.0f ? v : expm1f(v); }
__device__ __forceinline__ float bf16_round(float v) {
    return __bfloat162float(__float2bfloat16_rn(v));
}
// pack {lo, hi}: lower 16 bits = bf16(lo)
__device__ __forceinline__ uint32_t pack_bf16x2(float lo, float hi) {
    uint32_t r;
    asm("cvt.rn.bf16x2.f32 %0, %1, %2;" : "=r"(r) : "f"(hi), "f"(lo));
    return r;
}
__device__ __forceinline__ void mma_bf16(float* c, const uint32_t* a, uint32_t b0, uint32_t b1) {
    asm volatile("mma.sync.aligned.m16n8k16.row.col.f32.bf16.bf16.f32 "
                 "{%0,%1,%2,%3}, {%4,%5,%6,%7}, {%8,%9}, {%0,%1,%2,%3};"
                 : "+f"(c[0]), "+f"(c[1]), "+f"(c[2]), "+f"(c[3])
                 : "r"(a[0]), "r"(a[1]), "r"(a[2]), "r"(a[3]), "r"(b0), "r"(b1));
}
__device__ __forceinline__ void ldsm4(uint32_t* r, uint32_t addr) {
    asm volatile("ldmatrix.sync.aligned.m8n8.x4.shared.b16 {%0,%1,%2,%3}, [%4];"
                 : "=r"(r[0]), "=r"(r[1]), "=r"(r[2]), "=r"(r[3]) : "r"(addr));
}
__device__ __forceinline__ void cp16(uint32_t dst, const void* src) {
    asm volatile("cp.async.ca.shared.global [%0], [%1], 16;" :: "r"(dst), "l"(src));
}
__device__ __forceinline__ void cp_commit() { asm volatile("cp.async.commit_group;"); }
__device__ __forceinline__ void cp_wait0()  { asm volatile("cp.async.wait_group 0;"); }

// ---------------- prep kernels ----------------
__global__ void zero_misc_kernel() {
    int i = blockIdx.x * blockDim.x + threadIdx.x;
    if (i < NN * RR) { g_cnt[i] = 0; g_fpos[i] = 0; }
    if (i < GG * DD) g_pool[i] = 0.0f;
    if (i < GG)      g_pcnt[i] = 0.0f;
}

__global__ __launch_bounds__(256) void count_kernel(const int* __restrict__ ei,
                                                    const int* __restrict__ et) {
    int e = blockIdx.x * blockDim.x + threadIdx.x;
    if (e >= EE) return;
    atomicAdd(&g_cnt[ei[EE + e] * RR + et[e]], 1);
}

// scan of per-(dst,rel) counts -> CSR offsets
__global__ __launch_bounds__(256) void scan1_kernel() {
    __shared__ int sh[256];
    int i = blockIdx.x * 256 + threadIdx.x;
    int deg = (i < NN * RR) ? g_cnt[i] : 0;
    sh[threadIdx.x] = deg;
    __syncthreads();
    #pragma unroll
    for (int s = 1; s < 256; s <<= 1) {
        int t = (threadIdx.x >= s) ? sh[threadIdx.x - s] : 0;
        __syncthreads();
        sh[threadIdx.x] += t;
        __syncthreads();
    }
    if (i < NN * RR) g_off[i] = sh[threadIdx.x] - deg;
    if (threadIdx.x == 255) g_bsum[blockIdx.x] = sh[255];
}

// parallel scan of block partials (single block, 512 threads)
__global__ __launch_bounds__(512) void scan2_kernel() {
    __shared__ int sh[512];
    __shared__ int carry;
    if (threadIdx.x == 0) carry = 0;
    __syncthreads();
    for (int c0 = 0; c0 < NB2; c0 += 512) {
        int i = c0 + threadIdx.x;
        int v = (i < NB2) ? g_bsum[i] : 0;
        sh[threadIdx.x] = v;
        __syncthreads();
        #pragma unroll
        for (int s = 1; s < 512; s <<= 1) {
            int t = (threadIdx.x >= s) ? sh[threadIdx.x - s] : 0;
            __syncthreads();
            sh[threadIdx.x] += t;
            __syncthreads();
        }
        if (i < NB2) g_bsum[i] = sh[threadIdx.x] - v + carry;
        int tot = sh[511];
        __syncthreads();
        if (threadIdx.x == 0) carry += tot;
        __syncthreads();
    }
}

__global__ __launch_bounds__(256) void scan3_kernel() {
    int i = blockIdx.x * 256 + threadIdx.x;
    if (i < NN * RR) g_off[i] += g_bsum[blockIdx.x];
}

__global__ __launch_bounds__(256) void fill_kernel(const int* __restrict__ ei,
                                                   const int* __restrict__ et) {
    int e = blockIdx.x * blockDim.x + threadIdx.x;
    if (e >= EE) return;
    int s = ei[e], d = ei[EE + e], t = et[e];
    int b = d * RR + t;
    int pos = g_off[b] + atomicAdd(&g_fpos[b], 1);
    g_eidx[pos] = s;
}

// transposed split-bf16 weights: Bt[l][n][k]
__global__ void prepB_kernel(const float* __restrict__ root_w, const float* __restrict__ rel_w) {
    int idx = blockIdx.x * blockDim.x + threadIdx.x;
    if (idx >= 3 * KTOT * DD) return;
    int l = idx / (KTOT * DD);
    int rem = idx - l * KTOT * DD;
    int k = rem / DD;
    int n = rem - k * DD;
    float b;
    if (k < DD) b = root_w[(size_t)l * DD * DD + k * DD + n];
    else {
        int r = (k - DD) >> 7, kk = (k - DD) & 127;
        b = rel_w[(((size_t)l * RR + r) * DD + kk) * DD + n];
    }
    __nv_bfloat16 hi = __float2bfloat16_rn(b);
    __nv_bfloat16 lo = __float2bfloat16_rn(b - __bfloat162float(hi));
    size_t o = (size_t)l * DD * KTOT + (size_t)n * KTOT + k;
    g_bh[o] = hi;
    g_bl[o] = lo;
}

// ---------------- fused RGCN layer: in-block gather + tensor-core GEMM ----------
// Smem: A region [0,40960): h-phase = 2 stages x (hi 10240 | lo 10240);
//                           agg-phase = 4 chunk buffers of 10240 (bf16 hi only).
//       B region [40960,81920): 2 stages x (hi 10240 | lo 10240).
// Rows padded to 80B -> conflict-free ldmatrix.
// mode 0: bias+BN+ELU | 1: bias+resid+BN+ELU | 2: bias+resid
#define SMEM_BYTES 81920
#define B_REG 40960

__global__ __launch_bounds__(256) void rgcn_layer_kernel(
    const float* __restrict__ hsrc, float* __restrict__ hdst,
    const __nv_bfloat16* __restrict__ Bhg, const __nv_bfloat16* __restrict__ Blg,
    const float* __restrict__ bias,
    const float* __restrict__ gamma, const float* __restrict__ beta,
    const float* __restrict__ mean, const float* __restrict__ var,
    int mode)
{
    extern __shared__ char smc[];
    const uint32_t smb = (uint32_t)__cvta_generic_to_shared(smc);

    const int tid = threadIdx.x;
    const int warp = tid >> 5, lane = tid & 31;
    const int wm = warp >> 2, wn = warp & 3;
    const int row0 = blockIdx.x * 128;

    float acc[4][4][4];
    #pragma unroll
    for (int i = 0; i < 4; i++)
        #pragma unroll
        for (int j = 0; j < 4; j++)
            #pragma unroll
            for (int k = 0; k < 4; k++) acc[i][j][k] = 0.0f;

    // ldmatrix per-thread bases (stage/chunk byte offsets added at use)
    uint32_t a_base[4];
    #pragma unroll
    for (int mt = 0; mt < 4; mt++) {
        int m = wm * 64 + mt * 16 + (lane & 15);
        a_base[mt] = smb + m * 80 + (lane >> 4) * 16;
    }
    uint32_t b_base[2];
    #pragma unroll
    for (int p = 0; p < 2; p++) {
        int n = wn * 32 + p * 16 + (lane & 7) + (lane >> 4) * 8;
        b_base[p] = smb + B_REG + n * 80 + ((lane >> 3) & 1) * 16;
    }

    // loader geometry: lc = 16B chunk (0..3), lr = row (0..63), rows lr & lr+64
    const int lc = tid & 3;
    const int lr = tid >> 2;
    float4 areg[4];

    #define LDGA(kc) {                                                            \
        int _k0 = (kc) * 32 + lc * 8;                                             \
        _Pragma("unroll")                                                         \
        for (int i = 0; i < 2; i++) {                                             \
            int grow = row0 + lr + 64 * i;                                        \
            if (grow >= NN) grow = NN - 1;                                        \
            areg[2*i]   = *(const float4*)(hsrc + (size_t)grow * DD + _k0);       \
            areg[2*i+1] = *(const float4*)(hsrc + (size_t)grow * DD + _k0 + 4);   \
        }                                                                         \
    }
    #define STSA(aoff) {                                                          \
        _Pragma("unroll")                                                         \
        for (int i = 0; i < 2; i++) {                                             \
            float4 v0 = areg[2*i], v1 = areg[2*i+1];                              \
            uint4 uh;                                                             \
            uh.x = pack_bf16x2(v0.x, v0.y);                                       \
            uh.y = pack_bf16x2(v0.z, v0.w);                                       \
            uh.z = pack_bf16x2(v1.x, v1.y);                                       \
            uh.w = pack_bf16x2(v1.z, v1.w);                                       \
            uint4 ul;                                                             \
            ul.x = pack_bf16x2(v0.x - bf16_round(v0.x), v0.y - bf16_round(v0.y)); \
            ul.y = pack_bf16x2(v0.z - bf16_round(v0.z), v0.w - bf16_round(v0.w)); \
            ul.z = pack_bf16x2(v1.x - bf16_round(v1.x), v1.y - bf16_round(v1.y)); \
            ul.w = pack_bf16x2(v1.z - bf16_round(v1.z), v1.w - bf16_round(v1.w)); \
            uint32_t off = (lr + 64*i) * 80u + lc * 16u + (aoff);                 \
            *(uint4*)(smc + off) = uh;                                            \
            *(uint4*)(smc + off + 10240) = ul;                                    \
        }                                                                         \
    }
    #define CPB(kc, boff) {                                                       \
        int _k0 = (kc) * 32 + lc * 8;                                             \
        _Pragma("unroll")                                                         \
        for (int i = 0; i < 2; i++) {                                             \
            int n = lr + 64 * i;                                                  \
            uint32_t off = n * 80u + lc * 16u + (boff);                           \
            cp16(smb + B_REG + off, Bhg + (size_t)n * KTOT + _k0);                \
            cp16(smb + B_REG + off + 10240, Blg + (size_t)n * KTOT + _k0);        \
        }                                                                         \
    }
    #define COMPUTE3(aoff, boff) {                                                \
        _Pragma("unroll")                                                         \
        for (int ks = 0; ks < 2; ks++) {                                          \
            uint32_t ah[4][4], al[4][4], bh[2][4], bl[2][4];                      \
            _Pragma("unroll")                                                     \
            for (int mt = 0; mt < 4; mt++) {                                      \
                ldsm4(ah[mt], a_base[mt] + (aoff) + ks * 32);                     \
                ldsm4(al[mt], a_base[mt] + (aoff) + 10240 + ks * 32);             \
            }                                                                     \
            _Pragma("unroll")                                                     \
            for (int p = 0; p < 2; p++) {                                         \
                ldsm4(bh[p], b_base[p] + (boff) + ks * 32);                       \
                ldsm4(bl[p], b_base[p] + (boff) + 10240 + ks * 32);               \
            }                                                                     \
            _Pragma("unroll")                                                     \
            for (int mt = 0; mt < 4; mt++)                                        \
                _Pragma("unroll")                                                 \
                for (int nt = 0; nt < 4; nt++) {                                  \
                    int p = nt >> 1, ix = (nt & 1) * 2;                           \
                    mma_bf16(acc[mt][nt], ah[mt], bh[p][ix], bh[p][ix+1]);        \
                    mma_bf16(acc[mt][nt], ah[mt], bl[p][ix], bl[p][ix+1]);        \
                    mma_bf16(acc[mt][nt], al[mt], bh[p][ix], bh[p][ix+1]);        \
                }                                                                 \
        }                                                                         \
    }
    #define COMPUTE2(aoff, boff) {                                                \
        _Pragma("unroll")                                                         \
        for (int ks = 0; ks < 2; ks++) {                                          \
            uint32_t ah[4][4], bh[2][4], bl[2][4];                                \
            _Pragma("unroll")                                                     \
            for (int mt = 0; mt < 4; mt++)                                        \
                ldsm4(ah[mt], a_base[mt] + (aoff) + ks * 32);                     \
            _Pragma("unroll")                                                     \
            for (int p = 0; p < 2; p++) {                                         \
                ldsm4(bh[p], b_base[p] + (boff) + ks * 32);                       \
                ldsm4(bl[p], b_base[p] + (boff) + 10240 + ks * 32);               \
            }                                                                     \
            _Pragma("unroll")                                                     \
            for (int mt = 0; mt < 4; mt++)                                        \
                _Pragma("unroll")                                                 \
                for (int nt = 0; nt < 4; nt++) {                                  \
                    int p = nt >> 1, ix = (nt & 1) * 2;                           \
                    mma_bf16(acc[mt][nt], ah[mt], bh[p][ix], bh[p][ix+1]);        \
                    mma_bf16(acc[mt][nt], ah[mt], bl[p][ix], bl[p][ix+1]);        \
                }                                                                 \
        }                                                                         \
    }

    // ---- h-phase: kc = 0..3, A = fp32 h -> bf16 hi/lo, 3-term ----
    LDGA(0);
    CPB(0, 0); cp_commit();
    STSA(0);
    cp_wait0();
    __syncthreads();

    #pragma unroll 1
    for (int kc = 0; kc < 4; kc++) {
        int s = kc & 1;
        if (kc < 3) { LDGA(kc + 1); CPB(kc + 1, (s ^ 1) * 20480); cp_commit(); }
        else        { CPB(4, (s ^ 1) * 20480); cp_commit(); }
        COMPUTE3(s * 20480, s * 20480);
        if (kc < 3) STSA((s ^ 1) * 20480);
        cp_wait0();
        __syncthreads();
    }

    // ---- agg phases: r = 0..3 ----
    #pragma unroll 1
    for (int r = 0; r < 4; r++) {
        // in-block gather: warp handles 16 dst rows, writes bf16 agg into A chunks
        {
            const uint32_t sta = (lane >> 3) * 10240u + ((lane & 7) >> 1) * 16u + (lane & 1) * 8u;
            #pragma unroll 1
            for (int i = 0; i < 16; i++) {
                int rowl = warp * 16 + i;
                int dst = row0 + rowl;
                float ax = 0.f, ay = 0.f, az = 0.f, aw = 0.f;
                int c = 0;
                if (dst < NN) {
                    int b = dst * RR + r;
                    int o0 = g_off[b];
                    int o1 = (b + 1 < NN * RR) ? g_off[b + 1] : EE;
                    c = o1 - o0;
                    for (int e = o0; e < o1; e++) {
                        int s = g_eidx[e];
                        const float4 v = *(const float4*)(hsrc + (size_t)s * DD + lane * 4);
                        ax += v.x; ay += v.y; az += v.z; aw += v.w;
                    }
                }
                float w = 1.0f / (float)(c > 1 ? c : 1);
                uint2 u;
                u.x = pack_bf16x2(ax * w, ay * w);
                u.y = pack_bf16x2(az * w, aw * w);
                *(uint2*)(smc + sta + rowl * 80u) = u;
            }
        }
        __syncthreads();

        // mma over this relation's 4 k-chunks
        #pragma unroll 1
        for (int j = 0; j < 4; j++) {
            int kc = 4 + 4 * r + j;
            int s = kc & 1;
            if (kc < 19) { CPB(kc + 1, (s ^ 1) * 20480); cp_commit(); }
            COMPUTE2(j * 10240, s * 20480);
            if (kc < 19) cp_wait0();
            __syncthreads();
        }
    }

    // ---- fused epilogue -> hdst ----
    #pragma unroll
    for (int nt = 0; nt < 4; nt++) {
        int col = wn * 32 + nt * 8 + ((lane & 3) << 1);
        float b0 = bias[col], b1 = bias[col + 1];
        float g0 = 0.f, g1 = 0.f, be0 = 0.f, be1 = 0.f, mu0 = 0.f, mu1 = 0.f, rs0 = 0.f, rs1 = 0.f;
        if (mode <= 1) {
            g0 = gamma[col]; g1 = gamma[col + 1];
            be0 = beta[col]; be1 = beta[col + 1];
            mu0 = mean[col]; mu1 = mean[col + 1];
            rs0 = rsqrtf(var[col] + 1e-5f); rs1 = rsqrtf(var[col + 1] + 1e-5f);
        }
        #pragma unroll
        for (int mt = 0; mt < 4; mt++) {
            #pragma unroll
            for (int half = 0; half < 2; half++) {
                int row = row0 + wm * 64 + mt * 16 + (lane >> 2) + half * 8;
                if (row >= NN) continue;
                float v0 = acc[mt][nt][half * 2 + 0] + b0;
                float v1 = acc[mt][nt][half * 2 + 1] + b1;
                if (mode >= 1) {
                    const float* rp = hsrc + (size_t)row * DD + col;
                    v0 += rp[0]; v1 += rp[1];
                }
                if (mode <= 1) {
                    v0 = elu1((v0 - mu0) * rs0 * g0 + be0);
                    v1 = elu1((v1 - mu1) * rs1 * g1 + be1);
                }
                float* hp = hdst + (size_t)row * DD + col;
                hp[0] = v0; hp[1] = v1;
            }
        }
    }
    #undef LDGA
    #undef STSA
    #undef CPB
    #undef COMPUTE3
    #undef COMPUTE2
}

// ---------------- pooling (batch sorted) ----------------
__global__ __launch_bounds__(256) void pool_kernel(const float* __restrict__ h,
                                                   const int* __restrict__ batch) {
    int warp = (blockIdx.x * blockDim.x + threadIdx.x) >> 5;
    int lane = threadIdx.x & 31;
    int n0 = warp * 32;
    if (n0 >= NN) return;
    int nend = n0 + 32 < NN ? n0 + 32 : NN;

    float4 acc = make_float4(0.f, 0.f, 0.f, 0.f);
    int cur = batch[n0];
    int cnt = 0;
    for (int n = n0; n < nend; n++) {
        int b = batch[n];
        if (b != cur) {
            red_add_v4(g_pool + cur * DD + lane * 4, acc.x, acc.y, acc.z, acc.w);
            if (lane == 0) atomicAdd(&g_pcnt[cur], (float)cnt);
            acc = make_float4(0.f, 0.f, 0.f, 0.f);
            cnt = 0;
            cur = b;
        }
        float4 v = *(const float4*)(h + (size_t)n * DD + lane * 4);
        acc.x += v.x; acc.y += v.y; acc.z += v.z; acc.w += v.w;
        cnt++;
    }
    red_add_v4(g_pool + cur * DD + lane * 4, acc.x, acc.y, acc.z, acc.w);
    if (lane == 0) atomicAdd(&g_pcnt[cur], (float)cnt);
}

// ---------------- classifier head ----------------
__global__ __launch_bounds__(64) void head_kernel(
    const float* __restrict__ W1, const float* __restrict__ b1,
    const float* __restrict__ W2, const float* __restrict__ b2,
    float* __restrict__ out)
{
    int g = blockIdx.x;
    __shared__ float p[DD];
    __shared__ float z[64];
    __shared__ float lg[CC];

    float inv = 1.0f / fmaxf(g_pcnt[g], 1.0f);
    for (int d = threadIdx.x; d < DD; d += 64) p[d] = g_pool[g * DD + d] * inv;
    __syncthreads();

    int j = threadIdx.x;
    float s = b1[j];
    #pragma unroll 4
    for (int d = 0; d < DD; d++) s += p[d] * W1[d * 64 + j];
    z[j] = elu1(s);
    __syncthreads();

    if (j < CC) {
        float t = b2[j];
        #pragma unroll 4
        for (int k = 0; k < 64; k++) t += z[k] * W2[k * CC + j];
        lg[j] = t;
    }
    __syncthreads();

    if (j < CC) {
        float m = -1e30f;
        #pragma unroll
        for (int c = 0; c < CC; c++) m = fmaxf(m, lg[c]);
        float se = 0.0f;
        #pragma unroll
        for (int c = 0; c < CC; c++) se += expf(lg[c] - m);
        out[g * CC + j] = lg[j] - m - logf(se);
    }
}

// ---------------- launch ----------------
extern "C" void kernel_launch(void* const* d_in, const int* in_sizes, int n_in,
                              void* d_out, int out_size) {
    const float* x        = (const float*)d_in[0];
    const int*   ei       = (const int*)d_in[1];
    const int*   et       = (const int*)d_in[2];
    const int*   batch    = (const int*)d_in[3];
    const float* rel_w    = (const float*)d_in[4];
    const float* root_w   = (const float*)d_in[5];
    const float* bias     = (const float*)d_in[6];
    const float* bn_gamma = (const float*)d_in[7];
    const float* bn_beta  = (const float*)d_in[8];
    const float* bn_mean  = (const float*)d_in[9];
    const float* bn_var   = (const float*)d_in[10];
    const float* cls_w1   = (const float*)d_in[11];
    const float* cls_b1   = (const float*)d_in[12];
    const float* cls_w2   = (const float*)d_in[13];
    const float* cls_b2   = (const float*)d_in[14];
    float* out = (float*)d_out;

    static int smem_set = 0;
    if (!smem_set) {
        cudaFuncSetAttribute(rgcn_layer_kernel,
                             cudaFuncAttributeMaxDynamicSharedMemorySize, SMEM_BYTES);
        smem_set = 1;
    }

    void* p;
    cudaGetSymbolAddress(&p, g_bh);  const __nv_bfloat16* BH = (const __nv_bfloat16*)p;
    cudaGetSymbolAddress(&p, g_bl);  const __nv_bfloat16* BL = (const __nv_bfloat16*)p;
    cudaGetSymbolAddress(&p, g_h0);  float* H0 = (float*)p;
    cudaGetSymbolAddress(&p, g_h1);  float* H1 = (float*)p;

    // prep: counts -> (dst,rel) CSR -> grouped edge list -> split weights
    zero_misc_kernel<<<(NN * RR + 255) / 256, 256>>>();
    count_kernel<<<(EE + 255) / 256, 256>>>(ei, et);
    scan1_kernel<<<NB2, 256>>>();
    scan2_kernel<<<1, 512>>>();
    scan3_kernel<<<NB2, 256>>>();
    fill_kernel<<<(EE + 255) / 256, 256>>>(ei, et);
    prepB_kernel<<<(3 * KTOT * DD + 255) / 256, 256>>>(root_w, rel_w);

    const int gmblocks = (NN + 127) / 128;
    const int pblocks  = (((NN + 31) / 32) * 32 + 255) / 256;

    // layer 0: x -> h0
    rgcn_layer_kernel<<<gmblocks, 256, SMEM_BYTES>>>(x, H0, BH, BL, bias,
                                                     bn_gamma, bn_beta, bn_mean, bn_var, 0);
    // layer 1: h0 -> h1 (residual + BN1 + ELU)
    rgcn_layer_kernel<<<gmblocks, 256, SMEM_BYTES>>>(H0, H1, BH + DD * KTOT, BL + DD * KTOT,
                                                     bias + DD, bn_gamma + DD, bn_beta + DD,
                                                     bn_mean + DD, bn_var + DD, 1);
    // layer 2: h1 -> h0 (residual only)
    rgcn_layer_kernel<<<gmblocks, 256, SMEM_BYTES>>>(H1, H0, BH + 2 * DD * KTOT,
                                                     BL + 2 * DD * KTOT, bias + 2 * DD,
                                                     bn_gamma, bn_beta, bn_mean, bn_var, 2);

    // pool + head
    pool_kernel<<<pblocks, 256>>>(H0, batch);
    head_kernel<<<GG, 64>>>(cls_w1, cls_b1, cls_w2, cls_b2, out);
}

// round 12
// speedup vs baseline: 1.6568x; 1.6568x over previous
#include <cuda_runtime.h>
#include <cuda_bf16.h>
#include <math.h>
#include <stdint.h>

// Problem constants
#define NN 100000
#define EE 600000
#define DD 128
#define RR 4
#define GG 256
#define CC 16
#define KTOT 640          // 128 (h) + 4*128 (per-relation aggregates)
#define NAGG 512          // agg cols
#define NB_SCAN 391       // ceil(NN/256)

// ---------------- device scratch ----------------
__device__ float          g_h0[(size_t)NN * DD];      // 51 MB
__device__ float          g_h1[(size_t)NN * DD];      // 51 MB
__device__ __nv_bfloat16  g_agg[(size_t)NN * NAGG];   // 102 MB
__device__ __nv_bfloat16  g_bh[3 * DD * KTOT];        // B hi bf16, [l][n][k]
__device__ __nv_bfloat16  g_bl[3 * DD * KTOT];        // B lo bf16
__device__ int    g_cnt[NN * RR];                     // per (dst,rel) in-degree
__device__ int    g_off[NN];                          // CSR row offsets (by dst)
__device__ int    g_fpos[NN];                         // fill tickets
__device__ int    g_bsum[512];                        // scan partials
__device__ int    g_eidx[EE];                         // packed (src<<2)|rel, dst-sorted
__device__ float  g_pool[GG * DD];
__device__ float  g_pcnt[GG];

// ---------------- helpers ----------------
__device__ __forceinline__ void red_add_v4(float* addr, float x, float y, float z, float w) {
    asm volatile("red.global.add.v4.f32 [%0], {%1,%2,%3,%4};"
                 :: "l"(addr), "f"(x), "f"(y), "f"(z), "f"(w) : "memory");
}
__device__ __forceinline__ float elu1(float v) { return v > 0.0f ? v : expm1f(v); }
__device__ __forceinline__ float bf16_round(float v) {
    return __bfloat162float(__float2bfloat16_rn(v));
}
// pack {lo, hi}: lower 16 bits = bf16(lo)
__device__ __forceinline__ uint32_t pack_bf16x2(float lo, float hi) {
    uint32_t r;
    asm("cvt.rn.bf16x2.f32 %0, %1, %2;" : "=r"(r) : "f"(hi), "f"(lo));
    return r;
}
__device__ __forceinline__ void mma_bf16(float* c, const uint32_t* a, uint32_t b0, uint32_t b1) {
    asm volatile("mma.sync.aligned.m16n8k16.row.col.f32.bf16.bf16.f32 "
                 "{%0,%1,%2,%3}, {%4,%5,%6,%7}, {%8,%9}, {%0,%1,%2,%3};"
                 : "+f"(c[0]), "+f"(c[1]), "+f"(c[2]), "+f"(c[3])
                 : "r"(a[0]), "r"(a[1]), "r"(a[2]), "r"(a[3]), "r"(b0), "r"(b1));
}
__device__ __forceinline__ void ldsm4(uint32_t* r, uint32_t addr) {
    asm volatile("ldmatrix.sync.aligned.m8n8.x4.shared.b16 {%0,%1,%2,%3}, [%4];"
                 : "=r"(r[0]), "=r"(r[1]), "=r"(r[2]), "=r"(r[3]) : "r"(addr));
}
__device__ __forceinline__ void cp16(uint32_t dst, const void* src) {
    asm volatile("cp.async.ca.shared.global [%0], [%1], 16;" :: "r"(dst), "l"(src));
}
__device__ __forceinline__ void cp_commit() { asm volatile("cp.async.commit_group;"); }
__device__ __forceinline__ void cp_wait0()  { asm volatile("cp.async.wait_group 0;"); }

// ---------------- prep kernels ----------------
__global__ void zero_misc_kernel() {
    int i = blockIdx.x * blockDim.x + threadIdx.x;
    if (i < NN * RR) g_cnt[i] = 0;
    if (i < NN)      g_fpos[i] = 0;
    if (i < GG * DD) g_pool[i] = 0.0f;
    if (i < GG)      g_pcnt[i] = 0.0f;
}

__global__ __launch_bounds__(256) void count_kernel(const int* __restrict__ ei,
                                                    const int* __restrict__ et) {
    int e = blockIdx.x * blockDim.x + threadIdx.x;
    if (e >= EE) return;
    atomicAdd(&g_cnt[ei[EE + e] * RR + et[e]], 1);
}

// block-level exclusive scan of per-dst degree (sum of 4 relation counts)
__global__ __launch_bounds__(256) void scan1_kernel() {
    __shared__ int sh[256];
    int i = blockIdx.x * 256 + threadIdx.x;
    int deg = 0;
    if (i < NN) {
        int4 c = *(const int4*)&g_cnt[4 * i];
        deg = c.x + c.y + c.z + c.w;
    }
    sh[threadIdx.x] = deg;
    __syncthreads();
    #pragma unroll
    for (int s = 1; s < 256; s <<= 1) {
        int t = (threadIdx.x >= s) ? sh[threadIdx.x - s] : 0;
        __syncthreads();
        sh[threadIdx.x] += t;
        __syncthreads();
    }
    if (i < NN) g_off[i] = sh[threadIdx.x] - deg;       // exclusive within block
    if (threadIdx.x == 255) g_bsum[blockIdx.x] = sh[255];
}

// parallel scan of block partials (single block, 512 threads, NB_SCAN=391 fits one pass)
__global__ __launch_bounds__(512) void scan2_kernel() {
    __shared__ int sh[512];
    int i = threadIdx.x;
    int v = (i < NB_SCAN) ? g_bsum[i] : 0;
    sh[i] = v;
    __syncthreads();
    #pragma unroll
    for (int s = 1; s < 512; s <<= 1) {
        int t = (i >= s) ? sh[i - s] : 0;
        __syncthreads();
        sh[i] += t;
        __syncthreads();
    }
    if (i < NB_SCAN) g_bsum[i] = sh[i] - v;             // exclusive
}

__global__ __launch_bounds__(256) void scan3_kernel() {
    int i = blockIdx.x * 256 + threadIdx.x;
    if (i < NN) g_off[i] += g_bsum[blockIdx.x];
}

__global__ __launch_bounds__(256) void fill_kernel(const int* __restrict__ ei,
                                                   const int* __restrict__ et) {
    int e = blockIdx.x * blockDim.x + threadIdx.x;
    if (e >= EE) return;
    int s = ei[e], d = ei[EE + e], t = et[e];
    int pos = g_off[d] + atomicAdd(&g_fpos[d], 1);
    g_eidx[pos] = (s << 2) | t;
}

// transposed split-bf16 weights: Bt[l][n][k]
__global__ void prepB_kernel(const float* __restrict__ root_w, const float* __restrict__ rel_w) {
    int idx = blockIdx.x * blockDim.x + threadIdx.x;
    if (idx >= 3 * KTOT * DD) return;
    int l = idx / (KTOT * DD);
    int rem = idx - l * KTOT * DD;
    int k = rem / DD;
    int n = rem - k * DD;
    float b;
    if (k < DD) b = root_w[(size_t)l * DD * DD + k * DD + n];
    else {
        int r = (k - DD) >> 7, kk = (k - DD) & 127;
        b = rel_w[(((size_t)l * RR + r) * DD + kk) * DD + n];
    }
    __nv_bfloat16 hi = __float2bfloat16_rn(b);
    __nv_bfloat16 lo = __float2bfloat16_rn(b - __bfloat162float(hi));
    size_t o = (size_t)l * DD * KTOT + (size_t)n * KTOT + k;
    g_bh[o] = hi;
    g_bl[o] = lo;
}

// ---------------- gather: warp per dst, CSR edges, write agg (bf16) once ----------
// unroll-by-2 over edges with independent accumulator sets for MLP.
__global__ __launch_bounds__(256) void gather_kernel(const float* __restrict__ hsrc) {
    int w = (blockIdx.x * blockDim.x + threadIdx.x) >> 5;
    int lane = threadIdx.x & 31;
    if (w >= NN) return;
    int off = g_off[w];
    int end = (w + 1 < NN) ? g_off[w + 1] : EE;

    // two independent accumulator banks per relation (a[r], b[r])
    float4 aa[RR], bb[RR];
    #pragma unroll
    for (int r = 0; r < RR; r++) {
        aa[r] = make_float4(0.f, 0.f, 0.f, 0.f);
        bb[r] = make_float4(0.f, 0.f, 0.f, 0.f);
    }

    int e = off;
    for (; e + 1 < end; e += 2) {
        int pk0 = g_eidx[e];
        int pk1 = g_eidx[e + 1];
        const float4 v0 = *(const float4*)(hsrc + (size_t)(pk0 >> 2) * DD + lane * 4);
        const float4 v1 = *(const float4*)(hsrc + (size_t)(pk1 >> 2) * DD + lane * 4);
        int r0 = pk0 & 3, r1 = pk1 & 3;
        aa[r0].x += v0.x; aa[r0].y += v0.y; aa[r0].z += v0.z; aa[r0].w += v0.w;
        bb[r1].x += v1.x; bb[r1].y += v1.y; bb[r1].z += v1.z; bb[r1].w += v1.w;
    }
    if (e < end) {
        int pk = g_eidx[e];
        const float4 v = *(const float4*)(hsrc + (size_t)(pk >> 2) * DD + lane * 4);
        int r = pk & 3;
        aa[r].x += v.x; aa[r].y += v.y; aa[r].z += v.z; aa[r].w += v.w;
    }

    int4 c = *(const int4*)&g_cnt[4 * w];
    float w0 = 1.0f / (float)(c.x > 1 ? c.x : 1);
    float w1 = 1.0f / (float)(c.y > 1 ? c.y : 1);
    float w2 = 1.0f / (float)(c.z > 1 ? c.z : 1);
    float w3 = 1.0f / (float)(c.w > 1 ? c.w : 1);

    __nv_bfloat16* ag = g_agg + (size_t)w * NAGG + lane * 4;
    uint2 u;
    u.x = pack_bf16x2((aa[0].x + bb[0].x) * w0, (aa[0].y + bb[0].y) * w0);
    u.y = pack_bf16x2((aa[0].z + bb[0].z) * w0, (aa[0].w + bb[0].w) * w0);
    *(uint2*)(ag + 0 * DD) = u;
    u.x = pack_bf16x2((aa[1].x + bb[1].x) * w1, (aa[1].y + bb[1].y) * w1);
    u.y = pack_bf16x2((aa[1].z + bb[1].z) * w1, (aa[1].w + bb[1].w) * w1);
    *(uint2*)(ag + 1 * DD) = u;
    u.x = pack_bf16x2((aa[2].x + bb[2].x) * w2, (aa[2].y + bb[2].y) * w2);
    u.y = pack_bf16x2((aa[2].z + bb[2].z) * w2, (aa[2].w + bb[2].w) * w2);
    *(uint2*)(ag + 2 * DD) = u;
    u.x = pack_bf16x2((aa[3].x + bb[3].x) * w3, (aa[3].y + bb[3].y) * w3);
    u.y = pack_bf16x2((aa[3].z + bb[3].z) * w3, (aa[3].w + bb[3].w) * w3);
    *(uint2*)(ag + 3 * DD) = u;
}

// ---------------- GEMM: C[N,128] = [h | agg] x B, mixed precision ----------------
// h k-chunks (kc 0..3): fp32 -> bf16 hi/lo split, 3-term mma.
// agg k-chunks (kc 4..19): bf16 direct cp.async as A-hi, 2-term mma.
// Block 128x128, 8 warps (2x4), warp tile 64x32. Smem rows padded to 80B.
// mode 0: bias+BN+ELU | 1: bias+resid+BN+ELU | 2: bias+resid
#define STG_STRIDE 10240
#define AH_OFF 0
#define AL_OFF 20480
#define BH_OFF 40960
#define BL_OFF 61440
#define SMEM_BYTES 81920

__global__ __launch_bounds__(256) void gemm_tc_kernel(
    const float* __restrict__ hsrc, float* __restrict__ hdst,
    const __nv_bfloat16* __restrict__ Bhg, const __nv_bfloat16* __restrict__ Blg,
    const float* __restrict__ bias,
    const float* __restrict__ gamma, const float* __restrict__ beta,
    const float* __restrict__ mean, const float* __restrict__ var,
    int mode)
{
    extern __shared__ char smc[];
    const uint32_t smb = (uint32_t)__cvta_generic_to_shared(smc);

    const int tid = threadIdx.x;
    const int warp = tid >> 5, lane = tid & 31;
    const int wm = warp >> 2, wn = warp & 3;
    const int row0 = blockIdx.x * 128;

    float acc[4][4][4];
    #pragma unroll
    for (int i = 0; i < 4; i++)
        #pragma unroll
        for (int j = 0; j < 4; j++)
            #pragma unroll
            for (int k = 0; k < 4; k++) acc[i][j][k] = 0.0f;

    // ldmatrix per-thread bases
    uint32_t a_addr[4];
    #pragma unroll
    for (int mt = 0; mt < 4; mt++) {
        int m = wm * 64 + mt * 16 + (lane & 15);
        a_addr[mt] = smb + AH_OFF + m * 80 + (lane >> 4) * 16;
    }
    uint32_t b_addr[2];
    #pragma unroll
    for (int p = 0; p < 2; p++) {
        int n = wn * 32 + p * 16 + (lane & 7) + (lane >> 4) * 8;
        b_addr[p] = smb + BH_OFF + n * 80 + ((lane >> 3) & 1) * 16;
    }

    // loader geometry: lc = 16B chunk (0..3), lr = row (0..63), rows lr & lr+64
    const int lc = tid & 3;
    const int lr = tid >> 2;
    float4 areg[4];

    #define LDGA(kc) {                                                            \
        int _k0 = (kc) * 32 + lc * 8;                                             \
        _Pragma("unroll")                                                         \
        for (int i = 0; i < 2; i++) {                                             \
            int grow = row0 + lr + 64 * i;                                        \
            if (grow >= NN) grow = NN - 1;                                        \
            areg[2*i]   = *(const float4*)(hsrc + (size_t)grow * DD + _k0);       \
            areg[2*i+1] = *(const float4*)(hsrc + (size_t)grow * DD + _k0 + 4);   \
        }                                                                         \
    }
    #define STSA(b) {                                                             \
        _Pragma("unroll")                                                         \
        for (int i = 0; i < 2; i++) {                                             \
            float4 v0 = areg[2*i], v1 = areg[2*i+1];                              \
            uint4 uh;                                                             \
            uh.x = pack_bf16x2(v0.x, v0.y);                                       \
            uh.y = pack_bf16x2(v0.z, v0.w);                                       \
            uh.z = pack_bf16x2(v1.x, v1.y);                                       \
            uh.w = pack_bf16x2(v1.z, v1.w);                                       \
            uint4 ul;                                                             \
            ul.x = pack_bf16x2(v0.x - bf16_round(v0.x), v0.y - bf16_round(v0.y)); \
            ul.y = pack_bf16x2(v0.z - bf16_round(v0.z), v0.w - bf16_round(v0.w)); \
            ul.z = pack_bf16x2(v1.x - bf16_round(v1.x), v1.y - bf16_round(v1.y)); \
            ul.w = pack_bf16x2(v1.z - bf16_round(v1.z), v1.w - bf16_round(v1.w)); \
            uint32_t off = (lr + 64*i) * 80u + lc * 16u + (b) * STG_STRIDE;       \
            *(uint4*)(smc + AH_OFF + off) = uh;                                   \
            *(uint4*)(smc + AL_OFF + off) = ul;                                   \
        }                                                                         \
    }
    #define CPA(kc, b) {                                                          \
        int _k0 = ((kc) - 4) * 32 + lc * 8;                                       \
        _Pragma("unroll")                                                         \
        for (int i = 0; i < 2; i++) {                                             \
            int grow = row0 + lr + 64 * i;                                        \
            if (grow >= NN) grow = NN - 1;                                        \
            uint32_t off = (lr + 64*i) * 80u + lc * 16u + (b) * STG_STRIDE;       \
            cp16(smb + AH_OFF + off, g_agg + (size_t)grow * NAGG + _k0);          \
        }                                                                         \
    }
    #define CPB(kc, b) {                                                          \
        int _k0 = (kc) * 32 + lc * 8;                                             \
        _Pragma("unroll")                                                         \
        for (int i = 0; i < 2; i++) {                                             \
            int n = lr + 64 * i;                                                  \
            uint32_t off = n * 80u + lc * 16u + (b) * STG_STRIDE;                 \
            cp16(smb + BH_OFF + off, Bhg + (size_t)n * KTOT + _k0);               \
            cp16(smb + BL_OFF + off, Blg + (size_t)n * KTOT + _k0);               \
        }                                                                         \
    }
    #define COMPUTE3(b) {                                                         \
        uint32_t bo = (b) * (uint32_t)STG_STRIDE;                                 \
        _Pragma("unroll")                                                         \
        for (int ks = 0; ks < 2; ks++) {                                          \
            uint32_t ah[4][4], al[4][4], bh[2][4], bl[2][4];                      \
            _Pragma("unroll")                                                     \
            for (int mt = 0; mt < 4; mt++) {                                      \
                ldsm4(ah[mt], a_addr[mt] + bo + ks * 32);                         \
                ldsm4(al[mt], a_addr[mt] + (AL_OFF - AH_OFF) + bo + ks * 32);     \
            }                                                                     \
            _Pragma("unroll")                                                     \
            for (int p = 0; p < 2; p++) {                                         \
                ldsm4(bh[p], b_addr[p] + bo + ks * 32);                           \
                ldsm4(bl[p], b_addr[p] + (BL_OFF - BH_OFF) + bo + ks * 32);       \
            }                                                                     \
            _Pragma("unroll")                                                     \
            for (int mt = 0; mt < 4; mt++)                                        \
                _Pragma("unroll")                                                 \
                for (int nt = 0; nt < 4; nt++) {                                  \
                    int p = nt >> 1, ix = (nt & 1) * 2;                           \
                    mma_bf16(acc[mt][nt], ah[mt], bh[p][ix], bh[p][ix+1]);        \
                    mma_bf16(acc[mt][nt], ah[mt], bl[p][ix], bl[p][ix+1]);        \
                    mma_bf16(acc[mt][nt], al[mt], bh[p][ix], bh[p][ix+1]);        \
                }                                                                 \
        }                                                                         \
    }
    #define COMPUTE2(b) {                                                         \
        uint32_t bo = (b) * (uint32_t)STG_STRIDE;                                 \
        _Pragma("unroll")                                                         \
        for (int ks = 0; ks < 2; ks++) {                                          \
            uint32_t ah[4][4], bh[2][4], bl[2][4];                                \
            _Pragma("unroll")                                                     \
            for (int mt = 0; mt < 4; mt++)                                        \
                ldsm4(ah[mt], a_addr[mt] + bo + ks * 32);                         \
            _Pragma("unroll")                                                     \
            for (int p = 0; p < 2; p++) {                                         \
                ldsm4(bh[p], b_addr[p] + bo + ks * 32);                           \
                ldsm4(bl[p], b_addr[p] + (BL_OFF - BH_OFF) + bo + ks * 32);       \
            }                                                                     \
            _Pragma("unroll")                                                     \
            for (int mt = 0; mt < 4; mt++)                                        \
                _Pragma("unroll")                                                 \
                for (int nt = 0; nt < 4; nt++) {                                  \
                    int p = nt >> 1, ix = (nt & 1) * 2;                           \
                    mma_bf16(acc[mt][nt], ah[mt], bh[p][ix], bh[p][ix+1]);        \
                    mma_bf16(acc[mt][nt], ah[mt], bl[p][ix], bl[p][ix+1]);        \
                }                                                                 \
        }                                                                         \
    }

    // prologue: stage kc=0 (h chunk)
    LDGA(0);
    CPB(0, 0); cp_commit();
    STSA(0);
    cp_wait0();
    __syncthreads();

    int buf = 0;
    // h-phase: kc = 0..3 (3-term)
    #pragma unroll 1
    for (int kc = 0; kc < 4; kc++) {
        if (kc < 3) { LDGA(kc + 1); CPB(kc + 1, buf ^ 1); cp_commit(); }
        else        { CPA(4, buf ^ 1); CPB(4, buf ^ 1); cp_commit(); }
        COMPUTE3(buf);
        if (kc < 3) STSA(buf ^ 1);
        cp_wait0();
        __syncthreads();
        buf ^= 1;
    }
    // agg-phase: kc = 4..19 (2-term, A-hi direct from agg)
    #pragma unroll 1
    for (int kc = 4; kc < 20; kc++) {
        if (kc < 19) { CPA(kc + 1, buf ^ 1); CPB(kc + 1, buf ^ 1); cp_commit(); }
        COMPUTE2(buf);
        if (kc < 19) cp_wait0();
        __syncthreads();
        buf ^= 1;
    }

    // fused epilogue -> hdst
    #pragma unroll
    for (int nt = 0; nt < 4; nt++) {
        int col = wn * 32 + nt * 8 + ((lane & 3) << 1);
        float b0 = bias[col], b1 = bias[col + 1];
        float g0 = 0.f, g1 = 0.f, be0 = 0.f, be1 = 0.f, mu0 = 0.f, mu1 = 0.f, rs0 = 0.f, rs1 = 0.f;
        if (mode <= 1) {
            g0 = gamma[col]; g1 = gamma[col + 1];
            be0 = beta[col]; be1 = beta[col + 1];
            mu0 = mean[col]; mu1 = mean[col + 1];
            rs0 = rsqrtf(var[col] + 1e-5f); rs1 = rsqrtf(var[col + 1] + 1e-5f);
        }
        #pragma unroll
        for (int mt = 0; mt < 4; mt++) {
            #pragma unroll
            for (int half = 0; half < 2; half++) {
                int row = row0 + wm * 64 + mt * 16 + (lane >> 2) + half * 8;
                if (row >= NN) continue;
                float v0 = acc[mt][nt][half * 2 + 0] + b0;
                float v1 = acc[mt][nt][half * 2 + 1] + b1;
                if (mode >= 1) {
                    const float* rp = hsrc + (size_t)row * DD + col;
                    v0 += rp[0]; v1 += rp[1];
                }
                if (mode <= 1) {
                    v0 = elu1((v0 - mu0) * rs0 * g0 + be0);
                    v1 = elu1((v1 - mu1) * rs1 * g1 + be1);
                }
                float* hp = hdst + (size_t)row * DD + col;
                hp[0] = v0; hp[1] = v1;
            }
        }
    }
    #undef LDGA
    #undef STSA
    #undef CPA
    #undef CPB
    #undef COMPUTE3
    #undef COMPUTE2
}

// ---------------- pooling (batch sorted) ----------------
__global__ __launch_bounds__(256) void pool_kernel(const float* __restrict__ h,
                                                   const int* __restrict__ batch) {
    int warp = (blockIdx.x * blockDim.x + threadIdx.x) >> 5;
    int lane = threadIdx.x & 31;
    int n0 = warp * 32;
    if (n0 >= NN) return;
    int nend = n0 + 32 < NN ? n0 + 32 : NN;

    float4 acc = make_float4(0.f, 0.f, 0.f, 0.f);
    int cur = batch[n0];
    int cnt = 0;
    for (int n = n0; n < nend; n++) {
        int b = batch[n];
        if (b != cur) {
            red_add_v4(g_pool + cur * DD + lane * 4, acc.x, acc.y, acc.z, acc.w);
            if (lane == 0) atomicAdd(&g_pcnt[cur], (float)cnt);
            acc = make_float4(0.f, 0.f, 0.f, 0.f);
            cnt = 0;
            cur = b;
        }
        float4 v = *(const float4*)(h + (size_t)n * DD + lane * 4);
        acc.x += v.x; acc.y += v.y; acc.z += v.z; acc.w += v.w;
        cnt++;
    }
    red_add_v4(g_pool + cur * DD + lane * 4, acc.x, acc.y, acc.z, acc.w);
    if (lane == 0) atomicAdd(&g_pcnt[cur], (float)cnt);
}

// ---------------- classifier head ----------------
__global__ __launch_bounds__(64) void head_kernel(
    const float* __restrict__ W1, const float* __restrict__ b1,
    const float* __restrict__ W2, const float* __restrict__ b2,
    float* __restrict__ out)
{
    int g = blockIdx.x;
    __shared__ float p[DD];
    __shared__ float z[64];
    __shared__ float lg[CC];

    float inv = 1.0f / fmaxf(g_pcnt[g], 1.0f);
    for (int d = threadIdx.x; d < DD; d += 64) p[d] = g_pool[g * DD + d] * inv;
    __syncthreads();

    int j = threadIdx.x;
    float s = b1[j];
    #pragma unroll 4
    for (int d = 0; d < DD; d++) s += p[d] * W1[d * 64 + j];
    z[j] = elu1(s);
    __syncthreads();

    if (j < CC) {
        float t = b2[j];
        #pragma unroll 4
        for (int k = 0; k < 64; k++) t += z[k] * W2[k * CC + j];
        lg[j] = t;
    }
    __syncthreads();

    if (j < CC) {
        float m = -1e30f;
        #pragma unroll
        for (int c = 0; c < CC; c++) m = fmaxf(m, lg[c]);
        float se = 0.0f;
        #pragma unroll
        for (int c = 0; c < CC; c++) se += expf(lg[c] - m);
        out[g * CC + j] = lg[j] - m - logf(se);
    }
}

// ---------------- launch ----------------
extern "C" void kernel_launch(void* const* d_in, const int* in_sizes, int n_in,
                              void* d_out, int out_size) {
    const float* x        = (const float*)d_in[0];
    const int*   ei       = (const int*)d_in[1];
    const int*   et       = (const int*)d_in[2];
    const int*   batch    = (const int*)d_in[3];
    const float* rel_w    = (const float*)d_in[4];
    const float* root_w   = (const float*)d_in[5];
    const float* bias     = (const float*)d_in[6];
    const float* bn_gamma = (const float*)d_in[7];
    const float* bn_beta  = (const float*)d_in[8];
    const float* bn_mean  = (const float*)d_in[9];
    const float* bn_var   = (const float*)d_in[10];
    const float* cls_w1   = (const float*)d_in[11];
    const float* cls_b1   = (const float*)d_in[12];
    const float* cls_w2   = (const float*)d_in[13];
    const float* cls_b2   = (const float*)d_in[14];
    float* out = (float*)d_out;

    static int smem_set = 0;
    if (!smem_set) {
        cudaFuncSetAttribute(gemm_tc_kernel,
                             cudaFuncAttributeMaxDynamicSharedMemorySize, SMEM_BYTES);
        smem_set = 1;
    }

    void* p;
    cudaGetSymbolAddress(&p, g_bh);  const __nv_bfloat16* BH = (const __nv_bfloat16*)p;
    cudaGetSymbolAddress(&p, g_bl);  const __nv_bfloat16* BL = (const __nv_bfloat16*)p;
    cudaGetSymbolAddress(&p, g_h0);  float* H0 = (float*)p;
    cudaGetSymbolAddress(&p, g_h1);  float* H1 = (float*)p;

    // prep: counts -> CSR scan -> dst-sorted edge list -> split weights
    zero_misc_kernel<<<(NN * RR + 255) / 256, 256>>>();
    count_kernel<<<(EE + 255) / 256, 256>>>(ei, et);
    scan1_kernel<<<NB_SCAN, 256>>>();
    scan2_kernel<<<1, 512>>>();
    scan3_kernel<<<NB_SCAN, 256>>>();
    fill_kernel<<<(EE + 255) / 256, 256>>>(ei, et);
    prepB_kernel<<<(3 * KTOT * DD + 255) / 256, 256>>>(root_w, rel_w);

    const int gablocks = (NN * 32 + 255) / 256;   // gather: warp per dst
    const int gmblocks = (NN + 127) / 128;
    const int pblocks  = (((NN + 31) / 32) * 32 + 255) / 256;

    // layer 0: x -> h0
    gather_kernel<<<gablocks, 256>>>(x);
    gemm_tc_kernel<<<gmblocks, 256, SMEM_BYTES>>>(x, H0, BH, BL, bias,
                                                  bn_gamma, bn_beta, bn_mean, bn_var, 0);
    // layer 1: h0 -> h1 (residual + BN1 + ELU)
    gather_kernel<<<gablocks, 256>>>(H0);
    gemm_tc_kernel<<<gmblocks, 256, SMEM_BYTES>>>(H0, H1, BH + DD * KTOT, BL + DD * KTOT,
                                                  bias + DD, bn_gamma + DD, bn_beta + DD,
                                                  bn_mean + DD, bn_var + DD, 1);
    // layer 2: h1 -> h0 (residual only)
    gather_kernel<<<gablocks, 256>>>(H1);
    gemm_tc_kernel<<<gmblocks, 256, SMEM_BYTES>>>(H1, H0, BH + 2 * DD * KTOT,
                                                  BL + 2 * DD * KTOT, bias + 2 * DD,
                                                  bn_gamma, bn_beta, bn_mean, bn_var, 2);

    // pool + head
    pool_kernel<<<pblocks, 256>>>(H0, batch);
    head_kernel<<<GG, 64>>>(cls_w1, cls_b1, cls_w2, cls_b2, out);
}

// round 13
// speedup vs baseline: 1.9697x; 1.1889x over previous
#include <cuda_runtime.h>
#include <cuda_bf16.h>
#include <math.h>
#include <stdint.h>

// Problem constants
#define NN 100000
#define EE 600000
#define DD 128
#define RR 4
#define GG 256
#define CC 16
#define KTOT 640          // 128 (h) + 4*128 (per-relation aggregates)
#define NAGG 512          // agg cols
#define NB_SCAN 391       // ceil(NN/256)

// ---------------- device scratch ----------------
__device__ float          g_h0[(size_t)NN * DD];      // 51 MB
__device__ float          g_h1[(size_t)NN * DD];      // 51 MB
__device__ __nv_bfloat16  g_agg[(size_t)NN * NAGG];   // 102 MB
__device__ __nv_bfloat16  g_bh[3 * DD * KTOT];        // B hi bf16, [l][n][k]
__device__ __nv_bfloat16  g_bl[3 * DD * KTOT];        // B lo bf16
__device__ int    g_cnt[NN * RR];                     // per (dst,rel) in-degree
__device__ int    g_off[NN];                          // CSR row offsets (by dst)
__device__ int    g_fpos[NN];                         // fill tickets
__device__ int    g_bsum[512];                        // scan partials
__device__ int    g_eidx[EE];                         // packed (src<<2)|rel, dst-sorted
__device__ float  g_pool[GG * DD];
__device__ float  g_pcnt[GG];

// ---------------- helpers ----------------
__device__ __forceinline__ void red_add_v4(float* addr, float x, float y, float z, float w) {
    asm volatile("red.global.add.v4.f32 [%0], {%1,%2,%3,%4};"
                 :: "l"(addr), "f"(x), "f"(y), "f"(z), "f"(w) : "memory");
}
__device__ __forceinline__ float elu1(float v) { return v > 0.0f ? v : expm1f(v); }
__device__ __forceinline__ float bf16_round(float v) {
    return __bfloat162float(__float2bfloat16_rn(v));
}
// pack {lo, hi}: lower 16 bits = bf16(lo)
__device__ __forceinline__ uint32_t pack_bf16x2(float lo, float hi) {
    uint32_t r;
    asm("cvt.rn.bf16x2.f32 %0, %1, %2;" : "=r"(r) : "f"(hi), "f"(lo));
    return r;
}
__device__ __forceinline__ void mma_bf16(float* c, const uint32_t* a, uint32_t b0, uint32_t b1) {
    asm volatile("mma.sync.aligned.m16n8k16.row.col.f32.bf16.bf16.f32 "
                 "{%0,%1,%2,%3}, {%4,%5,%6,%7}, {%8,%9}, {%0,%1,%2,%3};"
                 : "+f"(c[0]), "+f"(c[1]), "+f"(c[2]), "+f"(c[3])
                 : "r"(a[0]), "r"(a[1]), "r"(a[2]), "r"(a[3]), "r"(b0), "r"(b1));
}
__device__ __forceinline__ void ldsm4(uint32_t* r, uint32_t addr) {
    asm volatile("ldmatrix.sync.aligned.m8n8.x4.shared.b16 {%0,%1,%2,%3}, [%4];"
                 : "=r"(r[0]), "=r"(r[1]), "=r"(r[2]), "=r"(r[3]) : "r"(addr));
}
__device__ __forceinline__ void cp16(uint32_t dst, const void* src) {
    asm volatile("cp.async.ca.shared.global [%0], [%1], 16;" :: "r"(dst), "l"(src));
}
__device__ __forceinline__ void cp_commit() { asm volatile("cp.async.commit_group;"); }
__device__ __forceinline__ void cp_wait0()  { asm volatile("cp.async.wait_group 0;"); }

// ---------------- prep kernels ----------------
__global__ void zero_misc_kernel() {
    int i = blockIdx.x * blockDim.x + threadIdx.x;
    if (i < NN * RR) g_cnt[i] = 0;
    if (i < NN)      g_fpos[i] = 0;
    if (i < GG * DD) g_pool[i] = 0.0f;
    if (i < GG)      g_pcnt[i] = 0.0f;
}

__global__ __launch_bounds__(256) void count_kernel(const int* __restrict__ ei,
                                                    const int* __restrict__ et) {
    int e = blockIdx.x * blockDim.x + threadIdx.x;
    if (e >= EE) return;
    atomicAdd(&g_cnt[ei[EE + e] * RR + et[e]], 1);
}

// block-level exclusive scan of per-dst degree (sum of 4 relation counts)
__global__ __launch_bounds__(256) void scan1_kernel() {
    __shared__ int sh[256];
    int i = blockIdx.x * 256 + threadIdx.x;
    int deg = 0;
    if (i < NN) {
        int4 c = *(const int4*)&g_cnt[4 * i];
        deg = c.x + c.y + c.z + c.w;
    }
    sh[threadIdx.x] = deg;
    __syncthreads();
    #pragma unroll
    for (int s = 1; s < 256; s <<= 1) {
        int t = (threadIdx.x >= s) ? sh[threadIdx.x - s] : 0;
        __syncthreads();
        sh[threadIdx.x] += t;
        __syncthreads();
    }
    if (i < NN) g_off[i] = sh[threadIdx.x] - deg;       // exclusive within block
    if (threadIdx.x == 255) g_bsum[blockIdx.x] = sh[255];
}

// parallel scan of block partials (single block, 512 threads, NB_SCAN=391 fits one pass)
__global__ __launch_bounds__(512) void scan2_kernel() {
    __shared__ int sh[512];
    int i = threadIdx.x;
    int v = (i < NB_SCAN) ? g_bsum[i] : 0;
    sh[i] = v;
    __syncthreads();
    #pragma unroll
    for (int s = 1; s < 512; s <<= 1) {
        int t = (i >= s) ? sh[i - s] : 0;
        __syncthreads();
        sh[i] += t;
        __syncthreads();
    }
    if (i < NB_SCAN) g_bsum[i] = sh[i] - v;             // exclusive
}

__global__ __launch_bounds__(256) void scan3_kernel() {
    int i = blockIdx.x * 256 + threadIdx.x;
    if (i < NN) g_off[i] += g_bsum[blockIdx.x];
}

__global__ __launch_bounds__(256) void fill_kernel(const int* __restrict__ ei,
                                                   const int* __restrict__ et) {
    int e = blockIdx.x * blockDim.x + threadIdx.x;
    if (e >= EE) return;
    int s = ei[e], d = ei[EE + e], t = et[e];
    int pos = g_off[d] + atomicAdd(&g_fpos[d], 1);
    g_eidx[pos] = (s << 2) | t;
}

// transposed split-bf16 weights: Bt[l][n][k]
__global__ void prepB_kernel(const float* __restrict__ root_w, const float* __restrict__ rel_w) {
    int idx = blockIdx.x * blockDim.x + threadIdx.x;
    if (idx >= 3 * KTOT * DD) return;
    int l = idx / (KTOT * DD);
    int rem = idx - l * KTOT * DD;
    int k = rem / DD;
    int n = rem - k * DD;
    float b;
    if (k < DD) b = root_w[(size_t)l * DD * DD + k * DD + n];
    else {
        int r = (k - DD) >> 7, kk = (k - DD) & 127;
        b = rel_w[(((size_t)l * RR + r) * DD + kk) * DD + n];
    }
    __nv_bfloat16 hi = __float2bfloat16_rn(b);
    __nv_bfloat16 lo = __float2bfloat16_rn(b - __bfloat162float(hi));
    size_t o = (size_t)l * DD * KTOT + (size_t)n * KTOT + k;
    g_bh[o] = hi;
    g_bl[o] = lo;
}

// ---------------- gather: warp per dst, CSR edges, write agg (bf16) once ----------
// R7-proven form: branch dispatch into named scalar accumulators (all registers).
__global__ __launch_bounds__(256) void gather_kernel(const float* __restrict__ hsrc) {
    int w = (blockIdx.x * blockDim.x + threadIdx.x) >> 5;
    int lane = threadIdx.x & 31;
    if (w >= NN) return;
    int off = g_off[w];
    int end = (w + 1 < NN) ? g_off[w + 1] : EE;

    float a0x = 0.f, a0y = 0.f, a0z = 0.f, a0w = 0.f;
    float a1x = 0.f, a1y = 0.f, a1z = 0.f, a1w = 0.f;
    float a2x = 0.f, a2y = 0.f, a2z = 0.f, a2w = 0.f;
    float a3x = 0.f, a3y = 0.f, a3z = 0.f, a3w = 0.f;

    for (int e = off; e < end; e++) {
        int pk = g_eidx[e];
        const float4 v = *(const float4*)(hsrc + (size_t)(pk >> 2) * DD + lane * 4);
        int r = pk & 3;
        if (r == 0)      { a0x += v.x; a0y += v.y; a0z += v.z; a0w += v.w; }
        else if (r == 1) { a1x += v.x; a1y += v.y; a1z += v.z; a1w += v.w; }
        else if (r == 2) { a2x += v.x; a2y += v.y; a2z += v.z; a2w += v.w; }
        else             { a3x += v.x; a3y += v.y; a3z += v.z; a3w += v.w; }
    }

    int4 c = *(const int4*)&g_cnt[4 * w];
    float w0 = 1.0f / (float)(c.x > 1 ? c.x : 1);
    float w1 = 1.0f / (float)(c.y > 1 ? c.y : 1);
    float w2 = 1.0f / (float)(c.z > 1 ? c.z : 1);
    float w3 = 1.0f / (float)(c.w > 1 ? c.w : 1);

    __nv_bfloat16* ag = g_agg + (size_t)w * NAGG + lane * 4;
    uint2 u;
    u.x = pack_bf16x2(a0x * w0, a0y * w0); u.y = pack_bf16x2(a0z * w0, a0w * w0);
    *(uint2*)(ag + 0 * DD) = u;
    u.x = pack_bf16x2(a1x * w1, a1y * w1); u.y = pack_bf16x2(a1z * w1, a1w * w1);
    *(uint2*)(ag + 1 * DD) = u;
    u.x = pack_bf16x2(a2x * w2, a2y * w2); u.y = pack_bf16x2(a2z * w2, a2w * w2);
    *(uint2*)(ag + 2 * DD) = u;
    u.x = pack_bf16x2(a3x * w3, a3y * w3); u.y = pack_bf16x2(a3z * w3, a3w * w3);
    *(uint2*)(ag + 3 * DD) = u;
}

// ---------------- GEMM: C[N,128] = [h | agg] x B, mixed precision ----------------
// h k-chunks (kc 0..3): fp32 -> bf16 hi/lo split, 3-term mma.
// agg k-chunks (kc 4..19): bf16 direct cp.async as A-hi, 2-term mma.
// Block 128x128, 8 warps (2x4), warp tile 64x32. Smem rows padded to 80B.
// mode 0: bias+BN+ELU | 1: bias+resid+BN+ELU | 2: bias+resid
#define STG_STRIDE 10240
#define AH_OFF 0
#define AL_OFF 20480
#define BH_OFF 40960
#define BL_OFF 61440
#define SMEM_BYTES 81920

__global__ __launch_bounds__(256) void gemm_tc_kernel(
    const float* __restrict__ hsrc, float* __restrict__ hdst,
    const __nv_bfloat16* __restrict__ Bhg, const __nv_bfloat16* __restrict__ Blg,
    const float* __restrict__ bias,
    const float* __restrict__ gamma, const float* __restrict__ beta,
    const float* __restrict__ mean, const float* __restrict__ var,
    int mode)
{
    extern __shared__ char smc[];
    const uint32_t smb = (uint32_t)__cvta_generic_to_shared(smc);

    const int tid = threadIdx.x;
    const int warp = tid >> 5, lane = tid & 31;
    const int wm = warp >> 2, wn = warp & 3;
    const int row0 = blockIdx.x * 128;

    float acc[4][4][4];
    #pragma unroll
    for (int i = 0; i < 4; i++)
        #pragma unroll
        for (int j = 0; j < 4; j++)
            #pragma unroll
            for (int k = 0; k < 4; k++) acc[i][j][k] = 0.0f;

    // ldmatrix per-thread bases
    uint32_t a_addr[4];
    #pragma unroll
    for (int mt = 0; mt < 4; mt++) {
        int m = wm * 64 + mt * 16 + (lane & 15);
        a_addr[mt] = smb + AH_OFF + m * 80 + (lane >> 4) * 16;
    }
    uint32_t b_addr[2];
    #pragma unroll
    for (int p = 0; p < 2; p++) {
        int n = wn * 32 + p * 16 + (lane & 7) + (lane >> 4) * 8;
        b_addr[p] = smb + BH_OFF + n * 80 + ((lane >> 3) & 1) * 16;
    }

    // loader geometry: lc = 16B chunk (0..3), lr = row (0..63), rows lr & lr+64
    const int lc = tid & 3;
    const int lr = tid >> 2;
    float4 areg[4];

    #define LDGA(kc) {                                                            \
        int _k0 = (kc) * 32 + lc * 8;                                             \
        _Pragma("unroll")                                                         \
        for (int i = 0; i < 2; i++) {                                             \
            int grow = row0 + lr + 64 * i;                                        \
            if (grow >= NN) grow = NN - 1;                                        \
            areg[2*i]   = *(const float4*)(hsrc + (size_t)grow * DD + _k0);       \
            areg[2*i+1] = *(const float4*)(hsrc + (size_t)grow * DD + _k0 + 4);   \
        }                                                                         \
    }
    #define STSA(b) {                                                             \
        _Pragma("unroll")                                                         \
        for (int i = 0; i < 2; i++) {                                             \
            float4 v0 = areg[2*i], v1 = areg[2*i+1];                              \
            uint4 uh;                                                             \
            uh.x = pack_bf16x2(v0.x, v0.y);                                       \
            uh.y = pack_bf16x2(v0.z, v0.w);                                       \
            uh.z = pack_bf16x2(v1.x, v1.y);                                       \
            uh.w = pack_bf16x2(v1.z, v1.w);                                       \
            uint4 ul;                                                             \
            ul.x = pack_bf16x2(v0.x - bf16_round(v0.x), v0.y - bf16_round(v0.y)); \
            ul.y = pack_bf16x2(v0.z - bf16_round(v0.z), v0.w - bf16_round(v0.w)); \
            ul.z = pack_bf16x2(v1.x - bf16_round(v1.x), v1.y - bf16_round(v1.y)); \
            ul.w = pack_bf16x2(v1.z - bf16_round(v1.z), v1.w - bf16_round(v1.w)); \
            uint32_t off = (lr + 64*i) * 80u + lc * 16u + (b) * STG_STRIDE;       \
            *(uint4*)(smc + AH_OFF + off) = uh;                                   \
            *(uint4*)(smc + AL_OFF + off) = ul;                                   \
        }                                                                         \
    }
    #define CPA(kc, b) {                                                          \
        int _k0 = ((kc) - 4) * 32 + lc * 8;                                       \
        _Pragma("unroll")                                                         \
        for (int i = 0; i < 2; i++) {                                             \
            int grow = row0 + lr + 64 * i;                                        \
            if (grow >= NN) grow = NN - 1;                                        \
            uint32_t off = (lr + 64*i) * 80u + lc * 16u + (b) * STG_STRIDE;       \
            cp16(smb + AH_OFF + off, g_agg + (size_t)grow * NAGG + _k0);          \
        }                                                                         \
    }
    #define CPB(kc, b) {                                                          \
        int _k0 = (kc) * 32 + lc * 8;                                             \
        _Pragma("unroll")                                                         \
        for (int i = 0; i < 2; i++) {                                             \
            int n = lr + 64 * i;                                                  \
            uint32_t off = n * 80u + lc * 16u + (b) * STG_STRIDE;                 \
            cp16(smb + BH_OFF + off, Bhg + (size_t)n * KTOT + _k0);               \
            cp16(smb + BL_OFF + off, Blg + (size_t)n * KTOT + _k0);               \
        }                                                                         \
    }
    #define COMPUTE3(b) {                                                         \
        uint32_t bo = (b) * (uint32_t)STG_STRIDE;                                 \
        _Pragma("unroll")                                                         \
        for (int ks = 0; ks < 2; ks++) {                                          \
            uint32_t ah[4][4], al[4][4], bh[2][4], bl[2][4];                      \
            _Pragma("unroll")                                                     \
            for (int mt = 0; mt < 4; mt++) {                                      \
                ldsm4(ah[mt], a_addr[mt] + bo + ks * 32);                         \
                ldsm4(al[mt], a_addr[mt] + (AL_OFF - AH_OFF) + bo + ks * 32);     \
            }                                                                     \
            _Pragma("unroll")                                                     \
            for (int p = 0; p < 2; p++) {                                         \
                ldsm4(bh[p], b_addr[p] + bo + ks * 32);                           \
                ldsm4(bl[p], b_addr[p] + (BL_OFF - BH_OFF) + bo + ks * 32);       \
            }                                                                     \
            _Pragma("unroll")                                                     \
            for (int mt = 0; mt < 4; mt++)                                        \
                _Pragma("unroll")                                                 \
                for (int nt = 0; nt < 4; nt++) {                                  \
                    int p = nt >> 1, ix = (nt & 1) * 2;                           \
                    mma_bf16(acc[mt][nt], ah[mt], bh[p][ix], bh[p][ix+1]);        \
                    mma_bf16(acc[mt][nt], ah[mt], bl[p][ix], bl[p][ix+1]);        \
                    mma_bf16(acc[mt][nt], al[mt], bh[p][ix], bh[p][ix+1]);        \
                }                                                                 \
        }                                                                         \
    }
    #define COMPUTE2(b) {                                                         \
        uint32_t bo = (b) * (uint32_t)STG_STRIDE;                                 \
        _Pragma("unroll")                                                         \
        for (int ks = 0; ks < 2; ks++) {                                          \
            uint32_t ah[4][4], bh[2][4], bl[2][4];                                \
            _Pragma("unroll")                                                     \
            for (int mt = 0; mt < 4; mt++)                                        \
                ldsm4(ah[mt], a_addr[mt] + bo + ks * 32);                         \
            _Pragma("unroll")                                                     \
            for (int p = 0; p < 2; p++) {                                         \
                ldsm4(bh[p], b_addr[p] + bo + ks * 32);                           \
                ldsm4(bl[p], b_addr[p] + (BL_OFF - BH_OFF) + bo + ks * 32);       \
            }                                                                     \
            _Pragma("unroll")                                                     \
            for (int mt = 0; mt < 4; mt++)                                        \
                _Pragma("unroll")                                                 \
                for (int nt = 0; nt < 4; nt++) {                                  \
                    int p = nt >> 1, ix = (nt & 1) * 2;                           \
                    mma_bf16(acc[mt][nt], ah[mt], bh[p][ix], bh[p][ix+1]);        \
                    mma_bf16(acc[mt][nt], ah[mt], bl[p][ix], bl[p][ix+1]);        \
                }                                                                 \
        }                                                                         \
    }

    // prologue: stage kc=0 (h chunk)
    LDGA(0);
    CPB(0, 0); cp_commit();
    STSA(0);
    cp_wait0();
    __syncthreads();

    int buf = 0;
    // h-phase: kc = 0..3 (3-term)
    #pragma unroll 1
    for (int kc = 0; kc < 4; kc++) {
        if (kc < 3) { LDGA(kc + 1); CPB(kc + 1, buf ^ 1); cp_commit(); }
        else        { CPA(4, buf ^ 1); CPB(4, buf ^ 1); cp_commit(); }
        COMPUTE3(buf);
        if (kc < 3) STSA(buf ^ 1);
        cp_wait0();
        __syncthreads();
        buf ^= 1;
    }
    // agg-phase: kc = 4..19 (2-term, A-hi direct from agg)
    #pragma unroll 1
    for (int kc = 4; kc < 20; kc++) {
        if (kc < 19) { CPA(kc + 1, buf ^ 1); CPB(kc + 1, buf ^ 1); cp_commit(); }
        COMPUTE2(buf);
        if (kc < 19) cp_wait0();
        __syncthreads();
        buf ^= 1;
    }

    // fused epilogue -> hdst
    #pragma unroll
    for (int nt = 0; nt < 4; nt++) {
        int col = wn * 32 + nt * 8 + ((lane & 3) << 1);
        float b0 = bias[col], b1 = bias[col + 1];
        float g0 = 0.f, g1 = 0.f, be0 = 0.f, be1 = 0.f, mu0 = 0.f, mu1 = 0.f, rs0 = 0.f, rs1 = 0.f;
        if (mode <= 1) {
            g0 = gamma[col]; g1 = gamma[col + 1];
            be0 = beta[col]; be1 = beta[col + 1];
            mu0 = mean[col]; mu1 = mean[col + 1];
            rs0 = rsqrtf(var[col] + 1e-5f); rs1 = rsqrtf(var[col + 1] + 1e-5f);
        }
        #pragma unroll
        for (int mt = 0; mt < 4; mt++) {
            #pragma unroll
            for (int half = 0; half < 2; half++) {
                int row = row0 + wm * 64 + mt * 16 + (lane >> 2) + half * 8;
                if (row >= NN) continue;
                float v0 = acc[mt][nt][half * 2 + 0] + b0;
                float v1 = acc[mt][nt][half * 2 + 1] + b1;
                if (mode >= 1) {
                    const float* rp = hsrc + (size_t)row * DD + col;
                    v0 += rp[0]; v1 += rp[1];
                }
                if (mode <= 1) {
                    v0 = elu1((v0 - mu0) * rs0 * g0 + be0);
                    v1 = elu1((v1 - mu1) * rs1 * g1 + be1);
                }
                float* hp = hdst + (size_t)row * DD + col;
                hp[0] = v0; hp[1] = v1;
            }
        }
    }
    #undef LDGA
    #undef STSA
    #undef CPA
    #undef CPB
    #undef COMPUTE3
    #undef COMPUTE2
}

// ---------------- pooling (batch sorted) ----------------
__global__ __launch_bounds__(256) void pool_kernel(const float* __restrict__ h,
                                                   const int* __restrict__ batch) {
    int warp = (blockIdx.x * blockDim.x + threadIdx.x) >> 5;
    int lane = threadIdx.x & 31;
    int n0 = warp * 32;
    if (n0 >= NN) return;
    int nend = n0 + 32 < NN ? n0 + 32 : NN;

    float4 acc = make_float4(0.f, 0.f, 0.f, 0.f);
    int cur = batch[n0];
    int cnt = 0;
    for (int n = n0; n < nend; n++) {
        int b = batch[n];
        if (b != cur) {
            red_add_v4(g_pool + cur * DD + lane * 4, acc.x, acc.y, acc.z, acc.w);
            if (lane == 0) atomicAdd(&g_pcnt[cur], (float)cnt);
            acc = make_float4(0.f, 0.f, 0.f, 0.f);
            cnt = 0;
            cur = b;
        }
        float4 v = *(const float4*)(h + (size_t)n * DD + lane * 4);
        acc.x += v.x; acc.y += v.y; acc.z += v.z; acc.w += v.w;
        cnt++;
    }
    red_add_v4(g_pool + cur * DD + lane * 4, acc.x, acc.y, acc.z, acc.w);
    if (lane == 0) atomicAdd(&g_pcnt[cur], (float)cnt);
}

// ---------------- classifier head ----------------
__global__ __launch_bounds__(64) void head_kernel(
    const float* __restrict__ W1, const float* __restrict__ b1,
    const float* __restrict__ W2, const float* __restrict__ b2,
    float* __restrict__ out)
{
    int g = blockIdx.x;
    __shared__ float p[DD];
    __shared__ float z[64];
    __shared__ float lg[CC];

    float inv = 1.0f / fmaxf(g_pcnt[g], 1.0f);
    for (int d = threadIdx.x; d < DD; d += 64) p[d] = g_pool[g * DD + d] * inv;
    __syncthreads();

    int j = threadIdx.x;
    float s = b1[j];
    #pragma unroll 4
    for (int d = 0; d < DD; d++) s += p[d] * W1[d * 64 + j];
    z[j] = elu1(s);
    __syncthreads();

    if (j < CC) {
        float t = b2[j];
        #pragma unroll 4
        for (int k = 0; k < 64; k++) t += z[k] * W2[k * CC + j];
        lg[j] = t;
    }
    __syncthreads();

    if (j < CC) {
        float m = -1e30f;
        #pragma unroll
        for (int c = 0; c < CC; c++) m = fmaxf(m, lg[c]);
        float se = 0.0f;
        #pragma unroll
        for (int c = 0; c < CC; c++) se += expf(lg[c] - m);
        out[g * CC + j] = lg[j] - m - logf(se);
    }
}

// ---------------- launch ----------------
extern "C" void kernel_launch(void* const* d_in, const int* in_sizes, int n_in,
                              void* d_out, int out_size) {
    const float* x        = (const float*)d_in[0];
    const int*   ei       = (const int*)d_in[1];
    const int*   et       = (const int*)d_in[2];
    const int*   batch    = (const int*)d_in[3];
    const float* rel_w    = (const float*)d_in[4];
    const float* root_w   = (const float*)d_in[5];
    const float* bias     = (const float*)d_in[6];
    const float* bn_gamma = (const float*)d_in[7];
    const float* bn_beta  = (const float*)d_in[8];
    const float* bn_mean  = (const float*)d_in[9];
    const float* bn_var   = (const float*)d_in[10];
    const float* cls_w1   = (const float*)d_in[11];
    const float* cls_b1   = (const float*)d_in[12];
    const float* cls_w2   = (const float*)d_in[13];
    const float* cls_b2   = (const float*)d_in[14];
    float* out = (float*)d_out;

    static int smem_set = 0;
    if (!smem_set) {
        cudaFuncSetAttribute(gemm_tc_kernel,
                             cudaFuncAttributeMaxDynamicSharedMemorySize, SMEM_BYTES);
        smem_set = 1;
    }

    void* p;
    cudaGetSymbolAddress(&p, g_bh);  const __nv_bfloat16* BH = (const __nv_bfloat16*)p;
    cudaGetSymbolAddress(&p, g_bl);  const __nv_bfloat16* BL = (const __nv_bfloat16*)p;
    cudaGetSymbolAddress(&p, g_h0);  float* H0 = (float*)p;
    cudaGetSymbolAddress(&p, g_h1);  float* H1 = (float*)p;

    // prep: counts -> CSR scan -> dst-sorted edge list -> split weights
    zero_misc_kernel<<<(NN * RR + 255) / 256, 256>>>();
    count_kernel<<<(EE + 255) / 256, 256>>>(ei, et);
    scan1_kernel<<<NB_SCAN, 256>>>();
    scan2_kernel<<<1, 512>>>();
    scan3_kernel<<<NB_SCAN, 256>>>();
    fill_kernel<<<(EE + 255) / 256, 256>>>(ei, et);
    prepB_kernel<<<(3 * KTOT * DD + 255) / 256, 256>>>(root_w, rel_w);

    const int gablocks = (NN * 32 + 255) / 256;   // gather: warp per dst
    const int gmblocks = (NN + 127) / 128;
    const int pblocks  = (((NN + 31) / 32) * 32 + 255) / 256;

    // layer 0: x -> h0
    gather_kernel<<<gablocks, 256>>>(x);
    gemm_tc_kernel<<<gmblocks, 256, SMEM_BYTES>>>(x, H0, BH, BL, bias,
                                                  bn_gamma, bn_beta, bn_mean, bn_var, 0);
    // layer 1: h0 -> h1 (residual + BN1 + ELU)
    gather_kernel<<<gablocks, 256>>>(H0);
    gemm_tc_kernel<<<gmblocks, 256, SMEM_BYTES>>>(H0, H1, BH + DD * KTOT, BL + DD * KTOT,
                                                  bias + DD, bn_gamma + DD, bn_beta + DD,
                                                  bn_mean + DD, bn_var + DD, 1);
    // layer 2: h1 -> h0 (residual only)
    gather_kernel<<<gablocks, 256>>>(H1);
    gemm_tc_kernel<<<gmblocks, 256, SMEM_BYTES>>>(H1, H0, BH + 2 * DD * KTOT,
                                                  BL + 2 * DD * KTOT, bias + 2 * DD,
                                                  bn_gamma, bn_beta, bn_mean, bn_var, 2);

    // pool + head
    pool_kernel<<<pblocks, 256>>>(H0, batch);
    head_kernel<<<GG, 64>>>(cls_w1, cls_b1, cls_w2, cls_b2, out);
}

// round 17
// speedup vs baseline: 1.9838x; 1.0072x over previous
#include <cuda_runtime.h>
#include <cuda_bf16.h>
#include <math.h>
#include <stdint.h>

// Problem constants
#define NN 100000
#define EE 600000
#define DD 128
#define RR 4
#define GG 256
#define CC 16
#define KTOT 640          // 128 (h) + 4*128 (per-relation aggregates)
#define NAGG 512          // agg cols
#define NB_SCAN 391       // ceil(NN/256)

// ---------------- device scratch ----------------
__device__ float          g_h0[(size_t)NN * DD];      // 51 MB
__device__ float          g_h1[(size_t)NN * DD];      // 51 MB
__device__ __nv_bfloat16  g_hb16[(size_t)NN * DD];    // 25.6 MB bf16 shadow of current h
__device__ __nv_bfloat16  g_agg[(size_t)NN * NAGG];   // 102 MB
__device__ __nv_bfloat16  g_bh[3 * DD * KTOT];        // B hi bf16, [l][n][k]
__device__ __nv_bfloat16  g_bl[3 * DD * KTOT];        // B lo bf16
__device__ int    g_cnt[NN * RR];                     // per (dst,rel) in-degree
__device__ int    g_off[NN];                          // CSR row offsets (by dst)
__device__ int    g_fpos[NN];                         // fill tickets
__device__ int    g_bsum[512];                        // scan partials
__device__ int    g_eidx[EE];                         // packed (src<<2)|rel, dst-sorted
__device__ float  g_pool[GG * DD];
__device__ float  g_pcnt[GG];

// ---------------- helpers ----------------
__device__ __forceinline__ void red_add_v4(float* addr, float x, float y, float z, float w) {
    asm volatile("red.global.add.v4.f32 [%0], {%1,%2,%3,%4};"
                 :: "l"(addr), "f"(x), "f"(y), "f"(z), "f"(w) : "memory");
}
__device__ __forceinline__ float elu1(float v) { return v > 0.0f ? v : expm1f(v); }
// pack {lo, hi}: lower 16 bits = bf16(lo)
__device__ __forceinline__ uint32_t pack_bf16x2(float lo, float hi) {
    uint32_t r;
    asm("cvt.rn.bf16x2.f32 %0, %1, %2;" : "=r"(r) : "f"(hi), "f"(lo));
    return r;
}
__device__ __forceinline__ void mma_bf16(float* c, const uint32_t* a, uint32_t b0, uint32_t b1) {
    asm volatile("mma.sync.aligned.m16n8k16.row.col.f32.bf16.bf16.f32 "
                 "{%0,%1,%2,%3}, {%4,%5,%6,%7}, {%8,%9}, {%0,%1,%2,%3};"
                 : "+f"(c[0]), "+f"(c[1]), "+f"(c[2]), "+f"(c[3])
                 : "r"(a[0]), "r"(a[1]), "r"(a[2]), "r"(a[3]), "r"(b0), "r"(b1));
}
__device__ __forceinline__ void ldsm4(uint32_t* r, uint32_t addr) {
    asm volatile("ldmatrix.sync.aligned.m8n8.x4.shared.b16 {%0,%1,%2,%3}, [%4];"
                 : "=r"(r[0]), "=r"(r[1]), "=r"(r[2]), "=r"(r[3]) : "r"(addr));
}
__device__ __forceinline__ void cp16(uint32_t dst, const void* src) {
    asm volatile("cp.async.ca.shared.global [%0], [%1], 16;" :: "r"(dst), "l"(src));
}
__device__ __forceinline__ void cp_commit() { asm volatile("cp.async.commit_group;"); }
__device__ __forceinline__ void cp_wait0()  { asm volatile("cp.async.wait_group 0;"); }

// ---------------- prep kernels ----------------
__global__ void zero_misc_kernel() {
    int i = blockIdx.x * blockDim.x + threadIdx.x;
    if (i < NN * RR) g_cnt[i] = 0;
    if (i < NN)      g_fpos[i] = 0;
    if (i < GG * DD) g_pool[i] = 0.0f;
    if (i < GG)      g_pcnt[i] = 0.0f;
}

__global__ __launch_bounds__(256) void count_kernel(const int* __restrict__ ei,
                                                    const int* __restrict__ et) {
    int e = blockIdx.x * blockDim.x + threadIdx.x;
    if (e >= EE) return;
    atomicAdd(&g_cnt[ei[EE + e] * RR + et[e]], 1);
}

__global__ __launch_bounds__(256) void scan1_kernel() {
    __shared__ int sh[256];
    int i = blockIdx.x * 256 + threadIdx.x;
    int deg = 0;
    if (i < NN) {
        int4 c = *(const int4*)&g_cnt[4 * i];
        deg = c.x + c.y + c.z + c.w;
    }
    sh[threadIdx.x] = deg;
    __syncthreads();
    #pragma unroll
    for (int s = 1; s < 256; s <<= 1) {
        int t = (threadIdx.x >= s) ? sh[threadIdx.x - s] : 0;
        __syncthreads();
        sh[threadIdx.x] += t;
        __syncthreads();
    }
    if (i < NN) g_off[i] = sh[threadIdx.x] - deg;
    if (threadIdx.x == 255) g_bsum[blockIdx.x] = sh[255];
}

__global__ __launch_bounds__(512) void scan2_kernel() {
    __shared__ int sh[512];
    int i = threadIdx.x;
    int v = (i < NB_SCAN) ? g_bsum[i] : 0;
    sh[i] = v;
    __syncthreads();
    #pragma unroll
    for (int s = 1; s < 512; s <<= 1) {
        int t = (i >= s) ? sh[i - s] : 0;
        __syncthreads();
        sh[i] += t;
        __syncthreads();
    }
    if (i < NB_SCAN) g_bsum[i] = sh[i] - v;
}

__global__ __launch_bounds__(256) void scan3_kernel() {
    int i = blockIdx.x * 256 + threadIdx.x;
    if (i < NN) g_off[i] += g_bsum[blockIdx.x];
}

__global__ __launch_bounds__(256) void fill_kernel(const int* __restrict__ ei,
                                                   const int* __restrict__ et) {
    int e = blockIdx.x * blockDim.x + threadIdx.x;
    if (e >= EE) return;
    int s = ei[e], d = ei[EE + e], t = et[e];
    int pos = g_off[d] + atomicAdd(&g_fpos[d], 1);
    g_eidx[pos] = (s << 2) | t;
}

// transposed split-bf16 weights: Bt[l][n][k]
__global__ void prepB_kernel(const float* __restrict__ root_w, const float* __restrict__ rel_w) {
    int idx = blockIdx.x * blockDim.x + threadIdx.x;
    if (idx >= 3 * KTOT * DD) return;
    int l = idx / (KTOT * DD);
    int rem = idx - l * KTOT * DD;
    int k = rem / DD;
    int n = rem - k * DD;
    float b;
    if (k < DD) b = root_w[(size_t)l * DD * DD + k * DD + n];
    else {
        int r = (k - DD) >> 7, kk = (k - DD) & 127;
        b = rel_w[(((size_t)l * RR + r) * DD + kk) * DD + n];
    }
    __nv_bfloat16 hi = __float2bfloat16_rn(b);
    __nv_bfloat16 lo = __float2bfloat16_rn(b - __bfloat162float(hi));
    size_t o = (size_t)l * DD * KTOT + (size_t)n * KTOT + k;
    g_bh[o] = hi;
    g_bl[o] = lo;
}

// convert x -> bf16 shadow (layer-0 input)
__global__ __launch_bounds__(256) void cvtx_kernel(const float* __restrict__ x) {
    int idx = blockIdx.x * blockDim.x + threadIdx.x;
    if (idx >= NN * 32) return;
    int n = idx >> 5, c4 = (idx & 31) * 4;
    float4 v = *(const float4*)(x + (size_t)n * DD + c4);
    uint2 u;
    u.x = pack_bf16x2(v.x, v.y);
    u.y = pack_bf16x2(v.z, v.w);
    *(uint2*)(g_hb16 + (size_t)n * DD + c4) = u;
}

// ---------------- gather: warp per dst, reads bf16 h shadow, writes bf16 agg ----
__global__ __launch_bounds__(256) void gather_kernel() {
    int w = (blockIdx.x * blockDim.x + threadIdx.x) >> 5;
    int lane = threadIdx.x & 31;
    if (w >= NN) return;
    int off = g_off[w];
    int end = (w + 1 < NN) ? g_off[w + 1] : EE;

    float a0x = 0.f, a0y = 0.f, a0z = 0.f, a0w = 0.f;
    float a1x = 0.f, a1y = 0.f, a1z = 0.f, a1w = 0.f;
    float a2x = 0.f, a2y = 0.f, a2z = 0.f, a2w = 0.f;
    float a3x = 0.f, a3y = 0.f, a3z = 0.f, a3w = 0.f;

    for (int e = off; e < end; e++) {
        int pk = g_eidx[e];
        const uint2 u = *(const uint2*)(g_hb16 + (size_t)(pk >> 2) * DD + lane * 4);
        float2 p0 = __bfloat1622float2(*reinterpret_cast<const __nv_bfloat162*>(&u.x));
        float2 p1 = __bfloat1622float2(*reinterpret_cast<const __nv_bfloat162*>(&u.y));
        int r = pk & 3;
        if (r == 0)      { a0x += p0.x; a0y += p0.y; a0z += p1.x; a0w += p1.y; }
        else if (r == 1) { a1x += p0.x; a1y += p0.y; a1z += p1.x; a1w += p1.y; }
        else if (r == 2) { a2x += p0.x; a2y += p0.y; a2z += p1.x; a2w += p1.y; }
        else             { a3x += p0.x; a3y += p0.y; a3z += p1.x; a3w += p1.y; }
    }

    int4 c = *(const int4*)&g_cnt[4 * w];
    float w0 = 1.0f / (float)(c.x > 1 ? c.x : 1);
    float w1 = 1.0f / (float)(c.y > 1 ? c.y : 1);
    float w2 = 1.0f / (float)(c.z > 1 ? c.z : 1);
    float w3 = 1.0f / (float)(c.w > 1 ? c.w : 1);

    __nv_bfloat16* ag = g_agg + (size_t)w * NAGG + lane * 4;
    uint2 u;
    u.x = pack_bf16x2(a0x * w0, a0y * w0); u.y = pack_bf16x2(a0z * w0, a0w * w0);
    *(uint2*)(ag + 0 * DD) = u;
    u.x = pack_bf16x2(a1x * w1, a1y * w1); u.y = pack_bf16x2(a1z * w1, a1w * w1);
    *(uint2*)(ag + 1 * DD) = u;
    u.x = pack_bf16x2(a2x * w2, a2y * w2); u.y = pack_bf16x2(a2z * w2, a2w * w2);
    *(uint2*)(ag + 2 * DD) = u;
    u.x = pack_bf16x2(a3x * w3, a3y * w3); u.y = pack_bf16x2(a3z * w3, a3w * w3);
    *(uint2*)(ag + 3 * DD) = u;
}

// ---------------- GEMM: C[N,128] = [h16 | agg] x B, uniform 2-term bf16 ----------
// All 20 k-chunks: A (bf16) via cp.async (kc 0..3 from g_hb16, 4..19 from g_agg);
// B hi+lo 2-term mma. Block 128x128, 8 warps (2x4), warp tile 64x32.
// Smem rows padded to 80B. Stages: A[2] @0/10240, Bh[2] @20480, Bl[2] @40960.
// mode 0: bias+BN+ELU | 1: bias+resid+BN+ELU | 2: bias+resid
// wb16: also write bf16 shadow of output h (for next gather)
#define STG 10240
#define BH_OFF 20480
#define BL_OFF 40960
#define SMEM_BYTES 61440

__global__ __launch_bounds__(256) void gemm_tc_kernel(
    const float* __restrict__ hsrc, float* __restrict__ hdst,
    const __nv_bfloat16* __restrict__ Bhg, const __nv_bfloat16* __restrict__ Blg,
    const float* __restrict__ bias,
    const float* __restrict__ gamma, const float* __restrict__ beta,
    const float* __restrict__ mean, const float* __restrict__ var,
    int mode, int wb16)
{
    extern __shared__ char smc[];
    const uint32_t smb = (uint32_t)__cvta_generic_to_shared(smc);

    const int tid = threadIdx.x;
    const int warp = tid >> 5, lane = tid & 31;
    const int wm = warp >> 2, wn = warp & 3;
    const int row0 = blockIdx.x * 128;

    float acc[4][4][4];
    #pragma unroll
    for (int i = 0; i < 4; i++)
        #pragma unroll
        for (int j = 0; j < 4; j++)
            #pragma unroll
            for (int k = 0; k < 4; k++) acc[i][j][k] = 0.0f;

    // ldmatrix per-thread bases
    uint32_t a_addr[4];
    #pragma unroll
    for (int mt = 0; mt < 4; mt++) {
        int m = wm * 64 + mt * 16 + (lane & 15);
        a_addr[mt] = smb + m * 80 + (lane >> 4) * 16;
    }
    uint32_t b_addr[2];
    #pragma unroll
    for (int p = 0; p < 2; p++) {
        int n = wn * 32 + p * 16 + (lane & 7) + (lane >> 4) * 8;
        b_addr[p] = smb + BH_OFF + n * 80 + ((lane >> 3) & 1) * 16;
    }

    // loader geometry: lc = 16B chunk (0..3), lr = row (0..63), rows lr & lr+64
    const int lc = tid & 3;
    const int lr = tid >> 2;

    #define CPA(kc, b) {                                                          \
        _Pragma("unroll")                                                         \
        for (int i = 0; i < 2; i++) {                                             \
            int grow = row0 + lr + 64 * i;                                        \
            if (grow >= NN) grow = NN - 1;                                        \
            uint32_t off = (lr + 64*i) * 80u + lc * 16u + (b) * STG;              \
            const __nv_bfloat16* src = ((kc) < 4)                                 \
                ? (g_hb16 + (size_t)grow * DD + (kc) * 32 + lc * 8)               \
                : (g_agg + (size_t)grow * NAGG + ((kc) - 4) * 32 + lc * 8);       \
            cp16(smb + off, src);                                                 \
        }                                                                         \
    }
    #define CPB(kc, b) {                                                          \
        int _k0 = (kc) * 32 + lc * 8;                                             \
        _Pragma("unroll")                                                         \
        for (int i = 0; i < 2; i++) {                                             \
            int n = lr + 64 * i;                                                  \
            uint32_t off = n * 80u + lc * 16u + (b) * STG;                        \
            cp16(smb + BH_OFF + off, Bhg + (size_t)n * KTOT + _k0);               \
            cp16(smb + BL_OFF + off, Blg + (size_t)n * KTOT + _k0);               \
        }                                                                         \
    }
    #define COMPUTE2(b) {                                                         \
        uint32_t bo = (b) * (uint32_t)STG;                                        \
        _Pragma("unroll")                                                         \
        for (int ks = 0; ks < 2; ks++) {                                          \
            uint32_t ah[4][4], bh[2][4], bl[2][4];                                \
            _Pragma("unroll")                                                     \
            for (int mt = 0; mt < 4; mt++)                                        \
                ldsm4(ah[mt], a_addr[mt] + bo + ks * 32);                         \
            _Pragma("unroll")                                                     \
            for (int p = 0; p < 2; p++) {                                         \
                ldsm4(bh[p], b_addr[p] + bo + ks * 32);                           \
                ldsm4(bl[p], b_addr[p] + (BL_OFF - BH_OFF) + bo + ks * 32);       \
            }                                                                     \
            _Pragma("unroll")                                                     \
            for (int mt = 0; mt < 4; mt++)                                        \
                _Pragma("unroll")                                                 \
                for (int nt = 0; nt < 4; nt++) {                                  \
                    int p = nt >> 1, ix = (nt & 1) * 2;                           \
                    mma_bf16(acc[mt][nt], ah[mt], bh[p][ix], bh[p][ix+1]);        \
                    mma_bf16(acc[mt][nt], ah[mt], bl[p][ix], bl[p][ix+1]);        \
                }                                                                 \
        }                                                                         \
    }

    // prologue: stage chunk 0
    CPA(0, 0); CPB(0, 0); cp_commit();
    cp_wait0();
    __syncthreads();

    int buf = 0;
    #pragma unroll 1
    for (int kc = 0; kc < 20; kc++) {
        if (kc < 19) { CPA(kc + 1, buf ^ 1); CPB(kc + 1, buf ^ 1); cp_commit(); }
        COMPUTE2(buf);
        if (kc < 19) cp_wait0();
        __syncthreads();
        buf ^= 1;
    }

    // fused epilogue -> hdst (+ optional bf16 shadow)
    #pragma unroll
    for (int nt = 0; nt < 4; nt++) {
        int col = wn * 32 + nt * 8 + ((lane & 3) << 1);
        float b0 = bias[col], b1 = bias[col + 1];
        float g0 = 0.f, g1 = 0.f, be0 = 0.f, be1 = 0.f, mu0 = 0.f, mu1 = 0.f, rs0 = 0.f, rs1 = 0.f;
        if (mode <= 1) {
            g0 = gamma[col]; g1 = gamma[col + 1];
            be0 = beta[col]; be1 = beta[col + 1];
            mu0 = mean[col]; mu1 = mean[col + 1];
            rs0 = rsqrtf(var[col] + 1e-5f); rs1 = rsqrtf(var[col + 1] + 1e-5f);
        }
        #pragma unroll
        for (int mt = 0; mt < 4; mt++) {
            #pragma unroll
            for (int half = 0; half < 2; half++) {
                int row = row0 + wm * 64 + mt * 16 + (lane >> 2) + half * 8;
                if (row >= NN) continue;
                float v0 = acc[mt][nt][half * 2 + 0] + b0;
                float v1 = acc[mt][nt][half * 2 + 1] + b1;
                if (mode >= 1) {
                    const float* rp = hsrc + (size_t)row * DD + col;
                    v0 += rp[0]; v1 += rp[1];
                }
                if (mode <= 1) {
                    v0 = elu1((v0 - mu0) * rs0 * g0 + be0);
                    v1 = elu1((v1 - mu1) * rs1 * g1 + be1);
                }
                float* hp = hdst + (size_t)row * DD + col;
                hp[0] = v0; hp[1] = v1;
                if (wb16)
                    *(uint32_t*)(g_hb16 + (size_t)row * DD + col) = pack_bf16x2(v0, v1);
            }
        }
    }
    #undef CPA
    #undef CPB
    #undef COMPUTE2
}

// ---------------- pooling (batch sorted) ----------------
__global__ __launch_bounds__(256) void pool_kernel(const float* __restrict__ h,
                                                   const int* __restrict__ batch) {
    int warp = (blockIdx.x * blockDim.x + threadIdx.x) >> 5;
    int lane = threadIdx.x & 31;
    int n0 = warp * 32;
    if (n0 >= NN) return;
    int nend = n0 + 32 < NN ? n0 + 32 : NN;

    float4 acc = make_float4(0.f, 0.f, 0.f, 0.f);
    int cur = batch[n0];
    int cnt = 0;
    for (int n = n0; n < nend; n++) {
        int b = batch[n];
        if (b != cur) {
            red_add_v4(g_pool + cur * DD + lane * 4, acc.x, acc.y, acc.z, acc.w);
            if (lane == 0) atomicAdd(&g_pcnt[cur], (float)cnt);
            acc = make_float4(0.f, 0.f, 0.f, 0.f);
            cnt = 0;
            cur = b;
        }
        float4 v = *(const float4*)(h + (size_t)n * DD + lane * 4);
        acc.x += v.x; acc.y += v.y; acc.z += v.z; acc.w += v.w;
        cnt++;
    }
    red_add_v4(g_pool + cur * DD + lane * 4, acc.x, acc.y, acc.z, acc.w);
    if (lane == 0) atomicAdd(&g_pcnt[cur], (float)cnt);
}

// ---------------- classifier head ----------------
__global__ __launch_bounds__(64) void head_kernel(
    const float* __restrict__ W1, const float* __restrict__ b1,
    const float* __restrict__ W2, const float* __restrict__ b2,
    float* __restrict__ out)
{
    int g = blockIdx.x;
    __shared__ float p[DD];
    __shared__ float z[64];
    __shared__ float lg[CC];

    float inv = 1.0f / fmaxf(g_pcnt[g], 1.0f);
    for (int d = threadIdx.x; d < DD; d += 64) p[d] = g_pool[g * DD + d] * inv;
    __syncthreads();

    int j = threadIdx.x;
    float s = b1[j];
    #pragma unroll 4
    for (int d = 0; d < DD; d++) s += p[d] * W1[d * 64 + j];
    z[j] = elu1(s);
    __syncthreads();

    if (j < CC) {
        float t = b2[j];
        #pragma unroll 4
        for (int k = 0; k < 64; k++) t += z[k] * W2[k * CC + j];
        lg[j] = t;
    }
    __syncthreads();

    if (j < CC) {
        float m = -1e30f;
        #pragma unroll
        for (int c = 0; c < CC; c++) m = fmaxf(m, lg[c]);
        float se = 0.0f;
        #pragma unroll
        for (int c = 0; c < CC; c++) se += expf(lg[c] - m);
        out[g * CC + j] = lg[j] - m - logf(se);
    }
}

// ---------------- launch ----------------
extern "C" void kernel_launch(void* const* d_in, const int* in_sizes, int n_in,
                              void* d_out, int out_size) {
    const float* x        = (const float*)d_in[0];
    const int*   ei       = (const int*)d_in[1];
    const int*   et       = (const int*)d_in[2];
    const int*   batch    = (const int*)d_in[3];
    const float* rel_w    = (const float*)d_in[4];
    const float* root_w   = (const float*)d_in[5];
    const float* bias     = (const float*)d_in[6];
    const float* bn_gamma = (const float*)d_in[7];
    const float* bn_beta  = (const float*)d_in[8];
    const float* bn_mean  = (const float*)d_in[9];
    const float* bn_var   = (const float*)d_in[10];
    const float* cls_w1   = (const float*)d_in[11];
    const float* cls_b1   = (const float*)d_in[12];
    const float* cls_w2   = (const float*)d_in[13];
    const float* cls_b2   = (const float*)d_in[14];
    float* out = (float*)d_out;

    static int smem_set = 0;
    if (!smem_set) {
        cudaFuncSetAttribute(gemm_tc_kernel,
                             cudaFuncAttributeMaxDynamicSharedMemorySize, SMEM_BYTES);
        smem_set = 1;
    }

    void* p;
    cudaGetSymbolAddress(&p, g_bh);  const __nv_bfloat16* BH = (const __nv_bfloat16*)p;
    cudaGetSymbolAddress(&p, g_bl);  const __nv_bfloat16* BL = (const __nv_bfloat16*)p;
    cudaGetSymbolAddress(&p, g_h0);  float* H0 = (float*)p;
    cudaGetSymbolAddress(&p, g_h1);  float* H1 = (float*)p;

    // prep: counts -> CSR scan -> dst-sorted edge list -> split weights -> x shadow
    zero_misc_kernel<<<(NN * RR + 255) / 256, 256>>>();
    count_kernel<<<(EE + 255) / 256, 256>>>(ei, et);
    scan1_kernel<<<NB_SCAN, 256>>>();
    scan2_kernel<<<1, 512>>>();
    scan3_kernel<<<NB_SCAN, 256>>>();
    fill_kernel<<<(EE + 255) / 256, 256>>>(ei, et);
    prepB_kernel<<<(3 * KTOT * DD + 255) / 256, 256>>>(root_w, rel_w);
    cvtx_kernel<<<(NN * 32 + 255) / 256, 256>>>(x);

    const int gablocks = (NN * 32 + 255) / 256;   // gather: warp per dst
    const int gmblocks = (NN + 127) / 128;
    const int pblocks  = (((NN + 31) / 32) * 32 + 255) / 256;

    // layer 0: x -> h0 (epilogue refreshes bf16 shadow with h0)
    gather_kernel<<<gablocks, 256>>>();
    gemm_tc_kernel<<<gmblocks, 256, SMEM_BYTES>>>(x, H0, BH, BL, bias,
                                                  bn_gamma, bn_beta, bn_mean, bn_var, 0, 1);
    // layer 1: h0 -> h1 (residual + BN1 + ELU; shadow <- h1)
    gather_kernel<<<gablocks, 256>>>();
    gemm_tc_kernel<<<gmblocks, 256, SMEM_BYTES>>>(H0, H1, BH + DD * KTOT, BL + DD * KTOT,
                                                  bias + DD, bn_gamma + DD, bn_beta + DD,
                                                  bn_mean + DD, bn_var + DD, 1, 1);
    // layer 2: h1 -> h0 (residual only; no shadow needed)
    gather_kernel<<<gablocks, 256>>>();
    gemm_tc_kernel<<<gmblocks, 256, SMEM_BYTES>>>(H1, H0, BH + 2 * DD * KTOT,
                                                  BL + 2 * DD * KTOT, bias + 2 * DD,
                                                  bn_gamma, bn_beta, bn_mean, bn_var, 2, 0);

    // pool + head
    pool_kernel<<<pblocks, 256>>>(H0, batch);
    head_kernel<<<GG, 64>>>(cls_w1, cls_b1, cls_w2, cls_b2, out);
}